// round 8
// baseline (speedup 1.0000x reference)
#include <cuda_runtime.h>
#include <cstdint>
#include <math.h>

#define NN 30000
#define EE 100000
#define DD 200
#define RR 100
#define BB 50
#define OUT4 (4*DD)   // 800 packed output columns: k,q,v,s

typedef unsigned long long ULL;

// ---------------- packed f32x2 helpers (FFMA2: 2x fp32 FMA throughput) ----------------
__device__ __forceinline__ ULL pk2(float a, float b) {
  ULL r; asm("mov.b64 %0,{%1,%2};" : "=l"(r) : "f"(a), "f"(b)); return r;
}
__device__ __forceinline__ void upk2(ULL d, float& x, float& y) {
  asm("mov.b64 {%0,%1},%2;" : "=f"(x), "=f"(y) : "l"(d));
}
__device__ __forceinline__ void fma2(ULL& d, ULL a, ULL b) {
  asm("fma.rn.f32x2 %0,%1,%2,%0;" : "+l"(d) : "l"(a), "l"(b));
}

// ---------------- cp.async helpers ----------------
__device__ __forceinline__ void cpa16(unsigned dst, const void* src, int srcsize) {
  asm volatile("cp.async.cg.shared.global [%0], [%1], 16, %2;\n"
               :: "r"(dst), "l"(src), "r"(srcsize));
}
__device__ __forceinline__ void cpcommit() { asm volatile("cp.async.commit_group;"); }
template<int N> __device__ __forceinline__ void cpwait() {
  asm volatile("cp.async.wait_group %0;" :: "n"(N));
}
__device__ __forceinline__ unsigned smem_u32(const void* p) {
  return (unsigned)__cvta_generic_to_shared(p);
}

// ---------------- scratch (static device globals; no runtime alloc) ----------------
__device__ __align__(16) float g_M[RR*DD*DD];        // per-relation matrices, 16MB
__device__ __align__(16) float g_W4T[DD*OUT4];       // packed weights, k-major [200][800]
__device__ __align__(16) float g_XT[DD*NN];          // transposed X, k-major [200][30000]
__device__ float g_b4[OUT4];
__device__ __align__(16) float g_KQVS[4u*NN*DD];     // K|Q|V|S node features, 96MB
__device__ unsigned g_maxu[NN];
__device__ __align__(16) float g_agg[NN*DD];         // n_pre (merged) output
__device__ int g_cnt[RR];
__device__ int g_off[RR+1];
__device__ int g_cur[RR];
__device__ int g_eid[EE];
__device__ int g_cnt2[NN];      // dst histogram
__device__ int g_off2[NN+1];
__device__ int g_cur2[NN];
__device__ int g_p2[EE];        // e -> dst-sorted position
__device__ int g_src2[EE];      // src, dst-sorted
__device__ float g_att2[EE];    // att, dst-sorted
__device__ float g_colsum[DD];
__device__ float g_colsum2[DD];
__device__ float g_scale[DD];
__device__ float g_shift[DD];

// ---------------- biases: k/q/v elementwise; S bias folds -(loop_rel @ wS^T) ----------------
__global__ void k_packb(const float* __restrict__ kb, const float* __restrict__ qb,
                        const float* __restrict__ vb, const float* __restrict__ sb,
                        const float* __restrict__ loop, const float* __restrict__ sw) {
  int tid = threadIdx.x, blk = blockIdx.x;
  int g = blk*256 + tid;
  if (g < 600) {
    int z = g / DD, j = g - z*DD;
    g_b4[g] = (z==0)?kb[j]:(z==1)?qb[j]:vb[j];
  }
  int w = blk*8 + (tid >> 5);
  int lane = tid & 31;
  if (w < DD) {
    float acc = 0.f;
    for (int i = lane; i < DD; i += 32) acc = fmaf(loop[i], sw[(size_t)w*DD + i], acc);
    #pragma unroll
    for (int o = 16; o; o >>= 1) acc += __shfl_xor_sync(0xffffffffu, acc, o);
    if (lane == 0) g_b4[600 + w] = sb[w] - acc;
  }
}

// ---------------- pack weights k-major: g_W4T[i][o] = w_z[j][i], o=z*DD+j ----------------
__global__ void k_pack(const float* __restrict__ kw, const float* __restrict__ qw,
                       const float* __restrict__ vw, const float* __restrict__ sw) {
  int idx = blockIdx.x*blockDim.x + threadIdx.x;
  if (idx >= OUT4*DD) return;
  int i = idx / OUT4, o = idx - i*OUT4;
  int z = o / DD, j = o - z*DD;
  const float* w = (z==0)?kw:(z==1)?qw:(z==2)?vw:sw;
  g_W4T[idx] = w[(size_t)j*DD + i];
}

// ---------------- transpose X [NN][DD] -> g_XT [DD][NN] ----------------
__global__ void k_transX(const float* __restrict__ X) {
  __shared__ float t[32][33];
  int bx = blockIdx.x*32;   // n base
  int by = blockIdx.y*32;   // d base
  int tx = threadIdx.x, ty = threadIdx.y;
  #pragma unroll
  for (int i = 0; i < 32; i += 8) {
    int n = bx + ty + i, d = by + tx;
    t[ty+i][tx] = (n < NN && d < DD) ? X[(size_t)n*DD + d] : 0.f;
  }
  __syncthreads();
  #pragma unroll
  for (int i = 0; i < 32; i += 8) {
    int d = by + ty + i, n = bx + tx;
    if (d < DD && n < NN) g_XT[(size_t)d*NN + n] = t[tx][ty+i];
  }
}

// ---------------- fused GEMM -> K,Q,V,S (f32x2, cp.async double-buffered) ----------------
#define GBM 128
#define GBN 128
#define GBK 40
#define GSTAGE (GBK*GBM)          // 5120 floats per matrix stage
#define GEMM_SMEM (4*GSTAGE*4)    // 81920 B
__global__ __launch_bounds__(256) void k_gemm() {
  extern __shared__ __align__(16) float sm[];
  float* Abuf[2] = { sm,            sm + GSTAGE   };
  float* Bbuf[2] = { sm + 2*GSTAGE, sm + 3*GSTAGE };
  int row0 = blockIdx.x*GBM, col0 = blockIdx.y*GBN;
  int tid = threadIdx.x;

  auto issue = [&](int s, int b) {
    int k0 = s*GBK;
    unsigned ab = smem_u32(Abuf[b]);
    unsigned bbp = smem_u32(Bbuf[b]);
    #pragma unroll
    for (int l = 0; l < 5; l++) {
      int idx = tid + l*256;
      int r = idx >> 5, c = idx & 31;
      int gm = row0 + c*4;
      cpa16(ab + (unsigned)(r*GBM + c*4)*4,
            g_XT + (size_t)(k0+r)*NN + gm, (gm+3 < NN) ? 16 : 0);
    }
    #pragma unroll
    for (int l = 0; l < 5; l++) {
      int idx = tid + l*256;
      int r = idx >> 5, c = idx & 31;
      int go = col0 + c*4;
      cpa16(bbp + (unsigned)(r*GBN + c*4)*4,
            g_W4T + (size_t)(k0+r)*OUT4 + go, (go+3 < OUT4) ? 16 : 0);
    }
    cpcommit();
  };

  // 4x2 warps, 4x8 lanes, 8x8 thread tile
  int w = tid >> 5, lane = tid & 31;
  int wm = w & 3, wn = w >> 2;
  int lm = lane >> 3, ln = lane & 7;
  int m0 = wm*32 + lm*8;
  int n0 = wn*64 + ln*8;

  ULL acc[8][4];
  #pragma unroll
  for (int u = 0; u < 8; u++)
    #pragma unroll
    for (int v = 0; v < 4; v++) acc[u][v] = pk2(0.f, 0.f);

  issue(0, 0);
  #pragma unroll
  for (int s = 0; s < 5; s++) {
    int b = s & 1;
    if (s + 1 < 5) { issue(s+1, (s+1)&1); cpwait<1>(); }
    else          { cpwait<0>(); }
    __syncthreads();
    const float* A = Abuf[b];
    const float* B = Bbuf[b];
    #pragma unroll 4
    for (int kk = 0; kk < GBK; kk++) {
      float4 a0 = *(const float4*)&A[kk*GBM + m0];
      float4 a1 = *(const float4*)&A[kk*GBM + m0 + 4];
      float4 b0 = *(const float4*)&B[kk*GBN + n0];
      float4 b1 = *(const float4*)&B[kk*GBN + n0 + 4];
      ULL bb[4];
      bb[0] = ((const ULL*)&b0)[0]; bb[1] = ((const ULL*)&b0)[1];
      bb[2] = ((const ULL*)&b1)[0]; bb[3] = ((const ULL*)&b1)[1];
      float av[8] = {a0.x,a0.y,a0.z,a0.w,a1.x,a1.y,a1.z,a1.w};
      #pragma unroll
      for (int u = 0; u < 8; u++) {
        ULL aa = pk2(av[u], av[u]);
        #pragma unroll
        for (int v = 0; v < 4; v++) fma2(acc[u][v], aa, bb[v]);
      }
    }
    __syncthreads();
  }

  // epilogue: each thread owns 8 rows x 8 cols; cols never straddle a z-boundary (200%8==0)
  int o0 = col0 + n0;
  if (o0 < OUT4) {
    int z = o0 / DD, j0 = o0 - z*DD;
    float4 bi0 = *(const float4*)&g_b4[o0];
    float4 bi1 = *(const float4*)&g_b4[o0+4];
    float* outb = g_KQVS + (size_t)z*NN*DD + j0;
    #pragma unroll
    for (int u = 0; u < 8; u++) {
      int n = row0 + m0 + u;
      if (n >= NN) continue;
      float c0,c1,c2,c3,c4,c5,c6,c7;
      upk2(acc[u][0], c0, c1); upk2(acc[u][1], c2, c3);
      upk2(acc[u][2], c4, c5); upk2(acc[u][3], c6, c7);
      float4 s0 = make_float4(c0+bi0.x, c1+bi0.y, c2+bi0.z, c3+bi0.w);
      float4 s1 = make_float4(c4+bi1.x, c5+bi1.y, c6+bi1.z, c7+bi1.w);
      *(float4*)(outb + (size_t)n*DD)     = s0;
      *(float4*)(outb + (size_t)n*DD + 4) = s1;
    }
  }
}

// ---------------- init counters ----------------
__global__ void k_init() {
  int stride = gridDim.x*blockDim.x;
  int t0 = blockIdx.x*blockDim.x + threadIdx.x;
  for (int t = t0; t < NN; t += stride) {
    g_maxu[t] = 0x007FFFFFu;   // enc(-inf)
    g_cnt2[t] = 0; g_cur2[t] = 0;
  }
  for (int t = t0; t < RR; t += stride) { g_cnt[t] = 0; g_cur[t] = 0; }
  for (int t = t0; t < DD; t += stride) { g_colsum[t] = 0.f; g_colsum2[t] = 0.f; }
}

// ---------------- M_r = sum_b w_comp[r,b] * A_b  (register-cached) ----------------
__global__ __launch_bounds__(256) void k_compM(const float* __restrict__ A,
                                               const float* __restrict__ wc) {
  __shared__ float wsh[RR*BB];   // 20KB
  int tid = threadIdx.x;
  for (int idx = tid; idx < RR*BB; idx += 256) wsh[idx] = wc[idx];
  __syncthreads();
  int n = blockIdx.x*256 + tid;
  if (n >= DD*DD) return;
  float a[BB];
  #pragma unroll
  for (int b = 0; b < BB; b++) a[b] = A[(size_t)b*DD*DD + n];
  for (int r = 0; r < RR; r++) {
    float acc0 = 0.f, acc1 = 0.f;
    const float* wr = wsh + r*BB;
    #pragma unroll
    for (int b = 0; b < BB; b += 2) {
      acc0 = fmaf(wr[b],   a[b],   acc0);
      acc1 = fmaf(wr[b+1], a[b+1], acc1);
    }
    g_M[(size_t)r*DD*DD + n] = acc0 + acc1;
  }
}

// ---------------- histograms: by relation AND by dst ----------------
__global__ void k_hist(const int* __restrict__ et, const int* __restrict__ dst) {
  int e = blockIdx.x*blockDim.x + threadIdx.x;
  if (e < EE) {
    atomicAdd(&g_cnt[et[e]], 1);
    atomicAdd(&g_cnt2[dst[e]], 1);
  }
}
__global__ void k_scan() {
  if (threadIdx.x == 0) {
    int s = 0;
    for (int r = 0; r < RR; r++) { g_off[r] = s; s += g_cnt[r]; }
    g_off[RR] = s;
  }
}
// 1-block exclusive scan of g_cnt2[NN] -> g_off2
#define SC_CHUNK 30
__global__ __launch_bounds__(1024) void k_scan2() {
  __shared__ int ps[1024];
  int t = threadIdx.x;
  int base = t*SC_CHUNK;
  int s = 0;
  #pragma unroll
  for (int i = 0; i < SC_CHUNK; i++) { int idx = base+i; if (idx < NN) s += g_cnt2[idx]; }
  ps[t] = s;
  __syncthreads();
  for (int off = 1; off < 1024; off <<= 1) {
    int v = ps[t];
    int add = (t >= off) ? ps[t-off] : 0;
    __syncthreads();
    ps[t] = v + add;
    __syncthreads();
  }
  int run = (t > 0) ? ps[t-1] : 0;
  #pragma unroll
  for (int i = 0; i < SC_CHUNK; i++) {
    int idx = base+i;
    if (idx < NN) { g_off2[idx] = run; run += g_cnt2[idx]; }
  }
  if (t == 1023) g_off2[NN] = ps[1023];
}
__global__ void k_scatter(const int* __restrict__ et, const int* __restrict__ src,
                          const int* __restrict__ dst) {
  int e = blockIdx.x*blockDim.x + threadIdx.x;
  if (e < EE) {
    int t = et[e];
    int p = atomicAdd(&g_cur[t], 1);
    g_eid[g_off[t] + p] = e;
    int d = dst[e];
    int p2 = atomicAdd(&g_cur2[d], 1);
    int pos = g_off2[d] + p2;
    g_p2[e] = pos;
    g_src2[pos] = src[e];
  }
}

// ---------------- attention: att_e = k^T M_r q (f32x2, cp.async pipelined) ----------------
#define ABM 128
#define KST 204
#define AJT 7                       // 7 tiles of 32 cols (224 >= 200; tail zero-filled)
// smem floats: k_sh 128*204 | Msh 2*200*32 | q_t 2*128*32 | att 128 | 3*128 ints
#define ATT_SMEM ((ABM*KST + 2*DD*32 + 2*ABM*32 + ABM)*4 + 3*ABM*4)   // 190464 B
__global__ __launch_bounds__(512, 1) void k_att(const int* __restrict__ src,
                                                const int* __restrict__ dst) {
  extern __shared__ __align__(16) float sm[];
  float* k_sh   = sm;                       // [128][204]
  float* Msh    = k_sh + ABM*KST;           // [2][200][32]
  float* q_t    = Msh + 2*DD*32;            // [2][128][32]
  float* att_sh = q_t + 2*ABM*32;           // [128]
  int* es_src = (int*)(att_sh + ABM);
  int* es_dst = es_src + ABM;
  int* es_eid = es_dst + ABM;

  int r = blockIdx.x;
  int beg = g_off[r], end = g_off[r+1];
  int base = beg + blockIdx.y*ABM;
  if (base >= end) return;
  int m = end - base; if (m > ABM) m = ABM;
  int tid = threadIdx.x;
  if (tid < ABM) {
    int e = g_eid[base + ((tid < m) ? tid : 0)];
    es_eid[tid] = e;
    es_src[tid] = src[e];
    es_dst[tid] = dst[e];
    att_sh[tid] = 0.f;
  }
  __syncthreads();

  const float* Mr = g_M + (size_t)r*DD*DD;
  const float* Qbase = g_KQVS + (size_t)NN*DD;

  auto issueMQ = [&](int jt, int b) {
    int j0 = jt*32;
    unsigned mb = smem_u32(Msh + b*DD*32);
    unsigned qb = smem_u32(q_t + b*ABM*32);
    #pragma unroll
    for (int l = 0; l < 4; l++) {
      int idx = tid + l*512;
      if (idx < DD*8) {
        int i = idx >> 3, p = idx & 7;
        int col = j0 + p*4;
        cpa16(mb + (unsigned)(i*32 + p*4)*4, Mr + (size_t)i*DD + col,
              (col + 3 < DD) ? 16 : 0);
      }
    }
    #pragma unroll
    for (int l = 0; l < 2; l++) {
      int idx = tid + l*512;
      int e = idx >> 3, p = idx & 7;
      int col = j0 + p*4;
      cpa16(qb + (unsigned)(e*32 + p*4)*4, Qbase + (size_t)es_dst[e]*DD + col,
            (col + 3 < DD) ? 16 : 0);
    }
    cpcommit();
  };

  // gather K rows via cp.async (group), then first M/Q tile (group)
  {
    unsigned kb = smem_u32(k_sh);
    for (int idx = tid; idx < ABM*(DD/4); idx += 512) {
      int e = idx / (DD/4), p = idx - e*(DD/4);
      cpa16(kb + (unsigned)(e*KST + p*4)*4,
            g_KQVS + (size_t)es_src[e]*DD + p*4, 16);
    }
    cpcommit();
  }
  issueMQ(0, 0);

  int tx = tid & 3;          // 4 col-groups of 8
  int ty = tid >> 2;         // 0..127, 1 row each
  const float* krow = k_sh + ty*KST;

  for (int jt = 0; jt < AJT; jt++) {
    int b = jt & 1;
    if (jt + 1 < AJT) { issueMQ(jt+1, (jt+1)&1); cpwait<1>(); }
    else              { cpwait<0>(); }
    __syncthreads();
    const float* Mb = Msh + b*DD*32;
    const float* Qb = q_t + b*ABM*32;
    ULL a0 = pk2(0.f,0.f), a1 = pk2(0.f,0.f), a2 = pk2(0.f,0.f), a3 = pk2(0.f,0.f);
    #pragma unroll 4
    for (int kk = 0; kk < DD; kk++) {
      float a = krow[kk];
      ULL aa = pk2(a, a);
      float4 b0 = *(const float4*)&Mb[kk*32 + tx*8];
      float4 b1 = *(const float4*)&Mb[kk*32 + tx*8 + 4];
      fma2(a0, aa, ((const ULL*)&b0)[0]);
      fma2(a1, aa, ((const ULL*)&b0)[1]);
      fma2(a2, aa, ((const ULL*)&b1)[0]);
      fma2(a3, aa, ((const ULL*)&b1)[1]);
    }
    {
      float4 q0 = *(const float4*)&Qb[ty*32 + tx*8];
      float4 q1 = *(const float4*)&Qb[ty*32 + tx*8 + 4];
      float c0,c1,c2,c3,c4,c5,c6,c7;
      upk2(a0, c0, c1); upk2(a1, c2, c3);
      upk2(a2, c4, c5); upk2(a3, c6, c7);
      float p = c0*q0.x + c1*q0.y + c2*q0.z + c3*q0.w
              + c4*q1.x + c5*q1.y + c6*q1.z + c7*q1.w;
      p += __shfl_xor_sync(0xffffffffu, p, 1);
      p += __shfl_xor_sync(0xffffffffu, p, 2);
      if (tx == 0) att_sh[ty] += p;      // unique row per ty
    }
    __syncthreads();
  }
  if (tid < m) {
    float a = att_sh[tid];
    int e = es_eid[tid];
    g_att2[g_p2[e]] = a;    // write into dst-sorted order
    unsigned u = __float_as_uint(a);
    u = (u & 0x80000000u) ? ~u : (u | 0x80000000u);
    atomicMax(&g_maxu[es_dst[tid]], u);
  }
}

// ---------------- per-dst softmax + weighted V aggregation + S merge (no atomics) --------
__device__ __forceinline__ float decf(unsigned u) {
  return (u & 0x80000000u) ? __uint_as_float(u ^ 0x80000000u) : __uint_as_float(~u);
}
__global__ __launch_bounds__(128) void k_agg2() {
  int d = blockIdx.x;
  int beg = g_off2[d], end = g_off2[d+1];
  int t = threadIdx.x;   // t<100 active for 2 cols each
  float m = decf(g_maxu[d]);
  float denom = 0.f;
  float ax = 0.f, ay = 0.f;
  const float* Vbase = g_KQVS + (size_t)2*NN*DD;
  for (int i = beg; i < end; i++) {
    float ex = __expf(g_att2[i] - m);
    denom += ex;
    int s = g_src2[i];
    if (t < 100) {
      float2 v = *(const float2*)(Vbase + (size_t)s*DD + t*2);
      ax = fmaf(ex, v.x, ax);
      ay = fmaf(ex, v.y, ay);
    }
  }
  if (t < 100) {
    float inv = (1.f/3.f) / fmaxf(denom, 1e-30f);
    size_t off = (size_t)d*DD + t*2;
    const float* Sb = g_KQVS + (size_t)3*NN*DD;
    float2 sv = *(const float2*)(Sb + off);
    float2 o;
    o.x = sv.x*(1.f/3.f) + ax*inv;
    o.y = sv.y*(1.f/3.f) + ay*inv;
    *(float2*)(g_agg + off) = o;
  }
}

// ---------------- column stats ----------------
#define ST_ROWS 48
__global__ __launch_bounds__(256) void k_stats() {
  int c = threadIdx.x;
  int r0 = blockIdx.x*ST_ROWS;
  if (c >= DD) return;
  float s = 0.f, s2 = 0.f;
  int rmax = NN - r0; if (rmax > ST_ROWS) rmax = ST_ROWS;
  for (int lr = 0; lr < rmax; lr++) {
    float val = g_agg[(size_t)(r0+lr)*DD + c];
    s += val; s2 = fmaf(val, val, s2);
  }
  atomicAdd(&g_colsum[c], s);
  atomicAdd(&g_colsum2[c], s2);
}
__global__ void k_bnprep(const float* __restrict__ gamma, const float* __restrict__ beta) {
  int c = threadIdx.x;
  if (c < DD) {
    float mean = g_colsum[c] * (1.f/NN);
    float var  = g_colsum2[c] * (1.f/NN) - mean*mean;
    float sc = gamma[c] * rsqrtf(var + 1e-5f);
    g_scale[c] = sc;
    g_shift[c] = beta[c] - mean*sc;
  }
}
__global__ void k_bnout(float* __restrict__ out) {
  int idx = blockIdx.x*blockDim.x + threadIdx.x;
  if (idx < NN*DD) {
    int c = idx - (idx/DD)*DD;
    float y = g_agg[idx]*g_scale[c] + g_shift[c];
    float t;
    asm("tanh.approx.f32 %0, %1;" : "=f"(t) : "f"(y));
    out[idx] = t;
  }
}

// ---------------- r_out = r_feats @ wR^T + b ----------------
__global__ void k_rout(const float* __restrict__ rf, const float* __restrict__ wr,
                       const float* __restrict__ br, float* __restrict__ out) {
  __shared__ float xs[DD];
  int r = blockIdx.x;
  int tid = threadIdx.x;
  if (tid < DD) xs[tid] = rf[(size_t)r*DD + tid];
  __syncthreads();
  if (tid < DD) {
    float acc = br[tid];
    const float* wrow = wr + (size_t)tid*DD;
    for (int i = 0; i < DD; i++) acc = fmaf(xs[i], wrow[i], acc);
    out[(size_t)r*DD + tid] = acc;
  }
}

// ---------------- launcher ----------------
extern "C" void kernel_launch(void* const* d_in, const int* in_sizes, int n_in,
                              void* d_out, int out_size) {
  const float* n_in_feats = (const float*)d_in[0];
  const float* r_feats    = (const float*)d_in[1];
  const float* loop_rel   = (const float*)d_in[3];
  const float* rel_att    = (const float*)d_in[4];
  const float* w_comp     = (const float*)d_in[5];
  const float* wS_w = (const float*)d_in[10]; const float* wS_b = (const float*)d_in[11];
  const float* wR_w = (const float*)d_in[12]; const float* wR_b = (const float*)d_in[13];
  const float* k_w  = (const float*)d_in[14]; const float* k_b  = (const float*)d_in[15];
  const float* q_w  = (const float*)d_in[16]; const float* q_b  = (const float*)d_in[17];
  const float* v_w  = (const float*)d_in[18]; const float* v_b  = (const float*)d_in[19];
  const float* gamma = (const float*)d_in[20]; const float* beta = (const float*)d_in[21];
  const int* src   = (const int*)d_in[22];
  const int* dst   = (const int*)d_in[23];
  const int* etype = (const int*)d_in[24];
  float* out = (float*)d_out;

  cudaFuncSetAttribute(k_gemm, cudaFuncAttributeMaxDynamicSharedMemorySize, GEMM_SMEM);
  cudaFuncSetAttribute(k_att,  cudaFuncAttributeMaxDynamicSharedMemorySize, ATT_SMEM);

  k_packb<<<25, 256>>>(k_b, q_b, v_b, wS_b, loop_rel, wS_w);
  k_pack<<<(OUT4*DD + 255)/256, 256>>>(k_w, q_w, v_w, wS_w);
  {
    dim3 g((NN + 31)/32, (DD + 31)/32);
    k_transX<<<g, dim3(32, 8)>>>(n_in_feats);
  }
  {
    dim3 g((NN + GBM - 1)/GBM, (OUT4 + GBN - 1)/GBN);
    k_gemm<<<g, 256, GEMM_SMEM>>>();      // 4th launch -> ncu capture slot
  }
  k_init<<<256, 256>>>();
  k_compM<<<(DD*DD + 255)/256, 256>>>(rel_att, w_comp);
  k_hist<<<(EE+255)/256, 256>>>(etype, dst);
  k_scan<<<1, 32>>>();
  k_scan2<<<1, 1024>>>();
  k_scatter<<<(EE+255)/256, 256>>>(etype, src, dst);
  {
    dim3 g(RR, 16);
    k_att<<<g, 512, ATT_SMEM>>>(src, dst);
  }
  k_agg2<<<NN, 128>>>();
  k_stats<<<(NN + ST_ROWS - 1)/ST_ROWS, 256>>>();
  k_bnprep<<<1, 256>>>(gamma, beta);
  k_bnout<<<(NN*DD + 255)/256, 256>>>(out);
  k_rout<<<RR, 256>>>(r_feats, wR_w, wR_b, out + (size_t)NN*DD);
}

// round 9
// speedup vs baseline: 1.6018x; 1.6018x over previous
#include <cuda_runtime.h>
#include <cstdint>
#include <math.h>

#define NN 30000
#define EE 100000
#define DD 200
#define RR 100
#define BB 50
#define OUT4 (4*DD)   // 800 packed output columns: k,q,v,s

typedef unsigned long long ULL;

// ---------------- packed f32x2 helpers (FFMA2: 2x fp32 FMA throughput) ----------------
__device__ __forceinline__ ULL pk2(float a, float b) {
  ULL r; asm("mov.b64 %0,{%1,%2};" : "=l"(r) : "f"(a), "f"(b)); return r;
}
__device__ __forceinline__ void upk2(ULL d, float& x, float& y) {
  asm("mov.b64 {%0,%1},%2;" : "=f"(x), "=f"(y) : "l"(d));
}
__device__ __forceinline__ void fma2(ULL& d, ULL a, ULL b) {
  asm("fma.rn.f32x2 %0,%1,%2,%0;" : "+l"(d) : "l"(a), "l"(b));
}

// ---------------- scratch (static device globals; no runtime alloc) ----------------
__device__ __align__(16) float g_M[RR*DD*DD];        // per-relation matrices, 16MB
__device__ __align__(16) float g_W4T[DD*OUT4];       // packed weights, k-major [200][800]
__device__ __align__(16) float g_XT[DD*NN];          // transposed X, k-major [200][30000]
__device__ float g_b4[OUT4];
__device__ __align__(16) float g_KQVS[4u*NN*DD];     // K|Q|V|S node features, 96MB
__device__ unsigned g_maxu[NN];
__device__ __align__(16) float g_agg[NN*DD];         // n_pre (merged) output
__device__ int g_cnt[RR];
__device__ int g_off[RR+1];
__device__ int g_cur[RR];
__device__ int g_eid[EE];
__device__ int g_cnt2[NN];      // dst histogram
__device__ int g_off2[NN+1];
__device__ int g_cur2[NN];
__device__ int g_p2[EE];        // e -> dst-sorted position
__device__ int g_src2[EE];      // src, dst-sorted
__device__ float g_att2[EE];    // att, dst-sorted
__device__ float g_colsum[DD];
__device__ float g_colsum2[DD];
__device__ float g_scale[DD];
__device__ float g_shift[DD];

// ---------------- biases: k/q/v elementwise; S bias folds -(loop_rel @ wS^T) ----------------
__global__ void k_packb(const float* __restrict__ kb, const float* __restrict__ qb,
                        const float* __restrict__ vb, const float* __restrict__ sb,
                        const float* __restrict__ loop, const float* __restrict__ sw) {
  int tid = threadIdx.x, blk = blockIdx.x;
  int g = blk*256 + tid;
  if (g < 600) {
    int z = g / DD, j = g - z*DD;
    g_b4[g] = (z==0)?kb[j]:(z==1)?qb[j]:vb[j];
  }
  int w = blk*8 + (tid >> 5);
  int lane = tid & 31;
  if (w < DD) {
    float acc = 0.f;
    for (int i = lane; i < DD; i += 32) acc = fmaf(loop[i], sw[(size_t)w*DD + i], acc);
    #pragma unroll
    for (int o = 16; o; o >>= 1) acc += __shfl_xor_sync(0xffffffffu, acc, o);
    if (lane == 0) g_b4[600 + w] = sb[w] - acc;
  }
}

// ---------------- pack weights k-major: g_W4T[i][o] = w_z[j][i], o=z*DD+j ----------------
__global__ void k_pack(const float* __restrict__ kw, const float* __restrict__ qw,
                       const float* __restrict__ vw, const float* __restrict__ sw) {
  int idx = blockIdx.x*blockDim.x + threadIdx.x;
  if (idx >= OUT4*DD) return;
  int i = idx / OUT4, o = idx - i*OUT4;
  int z = o / DD, j = o - z*DD;
  const float* w = (z==0)?kw:(z==1)?qw:(z==2)?vw:sw;
  g_W4T[idx] = w[(size_t)j*DD + i];
}

// ---------------- transpose X [NN][DD] -> g_XT [DD][NN] ----------------
__global__ void k_transX(const float* __restrict__ X) {
  __shared__ float t[32][33];
  int bx = blockIdx.x*32;   // n base
  int by = blockIdx.y*32;   // d base
  int tx = threadIdx.x, ty = threadIdx.y;
  #pragma unroll
  for (int i = 0; i < 32; i += 8) {
    int n = bx + ty + i, d = by + tx;
    t[ty+i][tx] = (n < NN && d < DD) ? X[(size_t)n*DD + d] : 0.f;
  }
  __syncthreads();
  #pragma unroll
  for (int i = 0; i < 32; i += 8) {
    int d = by + ty + i, n = bx + tx;
    if (d < DD && n < NN) g_XT[(size_t)d*NN + n] = t[tx][ty+i];
  }
}

// ---------------- fused GEMM -> K,Q,V,S (f32x2, 2 k-phases, 2 blocks/SM) ----------------
#define GBM 128
#define GBN 128
#define GBK 100
#define GSTG (GBK*GBM)            // 12800 floats per matrix
#define GEMM_SMEM (2*GSTG*4)      // 102400 B
__global__ __launch_bounds__(256) void k_gemm() {
  extern __shared__ __align__(16) float sm[];
  float* As = sm;            // [100][128]
  float* Bs = sm + GSTG;     // [100][128]
  int row0 = blockIdx.x*GBM, col0 = blockIdx.y*GBN;
  int tid = threadIdx.x;

  // 4x2 warps, 4x8 lanes, 8x8 thread tile
  int w = tid >> 5, lane = tid & 31;
  int wm = w & 3, wn = w >> 2;
  int lm = lane >> 3, ln = lane & 7;
  int m0 = wm*32 + lm*8;
  int n0 = wn*64 + ln*8;

  ULL acc[8][4];
  #pragma unroll
  for (int u = 0; u < 8; u++)
    #pragma unroll
    for (int v = 0; v < 4; v++) acc[u][v] = pk2(0.f, 0.f);

  #pragma unroll
  for (int s = 0; s < 2; s++) {
    int k0 = s*GBK;
    __syncthreads();   // previous compute done before overwriting buffers
    #pragma unroll
    for (int l = 0; l < 13; l++) {
      int idx = tid + l*256;          // 3200 float4s per matrix
      if (idx < GSTG/4) {
        int r = idx >> 5, c = idx & 31;
        int gm = row0 + c*4;
        float4 f = make_float4(0.f,0.f,0.f,0.f);
        if (gm + 3 < NN) f = *(const float4*)(g_XT + (size_t)(k0+r)*NN + gm);
        *(float4*)&As[r*GBM + c*4] = f;
      }
    }
    #pragma unroll
    for (int l = 0; l < 13; l++) {
      int idx = tid + l*256;
      if (idx < GSTG/4) {
        int r = idx >> 5, c = idx & 31;
        int go = col0 + c*4;
        float4 f = make_float4(0.f,0.f,0.f,0.f);
        if (go + 3 < OUT4) f = *(const float4*)(g_W4T + (size_t)(k0+r)*OUT4 + go);
        *(float4*)&Bs[r*GBN + c*4] = f;
      }
    }
    __syncthreads();
    #pragma unroll 4
    for (int kk = 0; kk < GBK; kk++) {
      float4 a0 = *(const float4*)&As[kk*GBM + m0];
      float4 a1 = *(const float4*)&As[kk*GBM + m0 + 4];
      float4 b0 = *(const float4*)&Bs[kk*GBN + n0];
      float4 b1 = *(const float4*)&Bs[kk*GBN + n0 + 4];
      ULL bb[4];
      bb[0] = ((const ULL*)&b0)[0]; bb[1] = ((const ULL*)&b0)[1];
      bb[2] = ((const ULL*)&b1)[0]; bb[3] = ((const ULL*)&b1)[1];
      float av[8] = {a0.x,a0.y,a0.z,a0.w,a1.x,a1.y,a1.z,a1.w};
      #pragma unroll
      for (int u = 0; u < 8; u++) {
        ULL aa = pk2(av[u], av[u]);
        #pragma unroll
        for (int v = 0; v < 4; v++) fma2(acc[u][v], aa, bb[v]);
      }
    }
  }

  // epilogue: 8 rows x 8 cols per thread; cols never straddle a z-boundary (200%8==0)
  int o0 = col0 + n0;
  if (o0 < OUT4) {
    int z = o0 / DD, j0 = o0 - z*DD;
    float4 bi0 = *(const float4*)&g_b4[o0];
    float4 bi1 = *(const float4*)&g_b4[o0+4];
    float* outb = g_KQVS + (size_t)z*NN*DD + j0;
    #pragma unroll
    for (int u = 0; u < 8; u++) {
      int n = row0 + m0 + u;
      if (n >= NN) continue;
      float c0,c1,c2,c3,c4,c5,c6,c7;
      upk2(acc[u][0], c0, c1); upk2(acc[u][1], c2, c3);
      upk2(acc[u][2], c4, c5); upk2(acc[u][3], c6, c7);
      float4 s0 = make_float4(c0+bi0.x, c1+bi0.y, c2+bi0.z, c3+bi0.w);
      float4 s1 = make_float4(c4+bi1.x, c5+bi1.y, c6+bi1.z, c7+bi1.w);
      *(float4*)(outb + (size_t)n*DD)     = s0;
      *(float4*)(outb + (size_t)n*DD + 4) = s1;
    }
  }
}

// ---------------- init counters ----------------
__global__ void k_init() {
  int stride = gridDim.x*blockDim.x;
  int t0 = blockIdx.x*blockDim.x + threadIdx.x;
  for (int t = t0; t < NN; t += stride) {
    g_maxu[t] = 0x007FFFFFu;   // enc(-inf)
    g_cnt2[t] = 0; g_cur2[t] = 0;
  }
  for (int t = t0; t < RR; t += stride) { g_cnt[t] = 0; g_cur[t] = 0; }
  for (int t = t0; t < DD; t += stride) { g_colsum[t] = 0.f; g_colsum2[t] = 0.f; }
}

// ---------------- M_r = sum_b w_comp[r,b] * A_b  (register-cached) ----------------
__global__ __launch_bounds__(256) void k_compM(const float* __restrict__ A,
                                               const float* __restrict__ wc) {
  __shared__ float wsh[RR*BB];   // 20KB
  int tid = threadIdx.x;
  for (int idx = tid; idx < RR*BB; idx += 256) wsh[idx] = wc[idx];
  __syncthreads();
  int n = blockIdx.x*256 + tid;
  if (n >= DD*DD) return;
  float a[BB];
  #pragma unroll
  for (int b = 0; b < BB; b++) a[b] = A[(size_t)b*DD*DD + n];
  for (int r = 0; r < RR; r++) {
    float acc0 = 0.f, acc1 = 0.f;
    const float* wr = wsh + r*BB;
    #pragma unroll
    for (int b = 0; b < BB; b += 2) {
      acc0 = fmaf(wr[b],   a[b],   acc0);
      acc1 = fmaf(wr[b+1], a[b+1], acc1);
    }
    g_M[(size_t)r*DD*DD + n] = acc0 + acc1;
  }
}

// ---------------- histograms: by relation AND by dst ----------------
__global__ void k_hist(const int* __restrict__ et, const int* __restrict__ dst) {
  int e = blockIdx.x*blockDim.x + threadIdx.x;
  if (e < EE) {
    atomicAdd(&g_cnt[et[e]], 1);
    atomicAdd(&g_cnt2[dst[e]], 1);
  }
}
__global__ void k_scan() {
  if (threadIdx.x == 0) {
    int s = 0;
    for (int r = 0; r < RR; r++) { g_off[r] = s; s += g_cnt[r]; }
    g_off[RR] = s;
  }
}
// 1-block exclusive scan of g_cnt2[NN] -> g_off2
#define SC_CHUNK 30
__global__ __launch_bounds__(1024) void k_scan2() {
  __shared__ int ps[1024];
  int t = threadIdx.x;
  int base = t*SC_CHUNK;
  int s = 0;
  #pragma unroll
  for (int i = 0; i < SC_CHUNK; i++) { int idx = base+i; if (idx < NN) s += g_cnt2[idx]; }
  ps[t] = s;
  __syncthreads();
  for (int off = 1; off < 1024; off <<= 1) {
    int v = ps[t];
    int add = (t >= off) ? ps[t-off] : 0;
    __syncthreads();
    ps[t] = v + add;
    __syncthreads();
  }
  int run = (t > 0) ? ps[t-1] : 0;
  #pragma unroll
  for (int i = 0; i < SC_CHUNK; i++) {
    int idx = base+i;
    if (idx < NN) { g_off2[idx] = run; run += g_cnt2[idx]; }
  }
  if (t == 1023) g_off2[NN] = ps[1023];
}
__global__ void k_scatter(const int* __restrict__ et, const int* __restrict__ src,
                          const int* __restrict__ dst) {
  int e = blockIdx.x*blockDim.x + threadIdx.x;
  if (e < EE) {
    int t = et[e];
    int p = atomicAdd(&g_cur[t], 1);
    g_eid[g_off[t] + p] = e;
    int d = dst[e];
    int p2 = atomicAdd(&g_cur2[d], 1);
    int pos = g_off2[d] + p2;
    g_p2[e] = pos;
    g_src2[pos] = src[e];
  }
}

// ---------------- attention: att_e = k^T M_r q (f32x2), 512 threads ----------------
#define ABM 128
#define KST 204
#define ATT_SMEM ((ABM*KST + DD*64 + ABM*64 + ABM)*4 + 3*ABM*4)  // 190464 B
__global__ __launch_bounds__(512, 1) void k_att(const int* __restrict__ src,
                                                const int* __restrict__ dst) {
  extern __shared__ __align__(16) float sm[];
  float* k_sh   = sm;                 // [ABM][KST]
  float* Msh    = k_sh + ABM*KST;     // [DD][64] (reused as [DD][8] in remainder)
  float* q_t    = Msh + DD*64;        // [ABM][64] (reused as [ABM][8])
  float* att_sh = q_t + ABM*64;       // [ABM]
  int* es_src = (int*)(att_sh + ABM);
  int* es_dst = es_src + ABM;
  int* es_eid = es_dst + ABM;

  int r = blockIdx.x;
  int beg = g_off[r], end = g_off[r+1];
  int base = beg + blockIdx.y*ABM;
  if (base >= end) return;
  int m = end - base; if (m > ABM) m = ABM;
  int tid = threadIdx.x;
  if (tid < ABM) {
    int e = g_eid[base + ((tid < m) ? tid : 0)];
    es_eid[tid] = e;
    es_src[tid] = src[e];
    es_dst[tid] = dst[e];
    att_sh[tid] = 0.f;
  }
  __syncthreads();
  // gather K rows (float4) into padded smem
  for (int idx = tid; idx < ABM*(DD/4); idx += 512) {
    int e = idx / (DD/4), p = idx - e*(DD/4);
    *(float4*)(k_sh + e*KST + p*4) = *(const float4*)(g_KQVS + (size_t)es_src[e]*DD + p*4);
  }
  int tx = tid & 7;          // 8 col-groups of 8 -> 64-col tile
  int ty = tid >> 3;         // 0..63, 2 rows each -> 128 rows
  const float* Mr = g_M + (size_t)r*DD*DD;
  const float* Qbase = g_KQVS + (size_t)NN*DD;
  // --- 3 full 64-col tiles: cols 0..191 ---
  for (int jt = 0; jt < 3; jt++) {
    int j0 = jt*64;
    __syncthreads();
    for (int idx = tid; idx < DD*16; idx += 512) {
      int i = idx >> 4, p = idx & 15;
      *(float4*)(Msh + i*64 + p*4) = *(const float4*)(Mr + (size_t)i*DD + j0 + p*4);
    }
    for (int idx = tid; idx < ABM*16; idx += 512) {
      int e = idx >> 4, p = idx & 15;
      *(float4*)(q_t + e*64 + p*4) = *(const float4*)(Qbase + (size_t)es_dst[e]*DD + j0 + p*4);
    }
    __syncthreads();
    ULL acc[2][4];
    #pragma unroll
    for (int u = 0; u < 2; u++)
      #pragma unroll
      for (int v = 0; v < 4; v++) acc[u][v] = pk2(0.f, 0.f);
    const float* krow0 = k_sh + (ty*2+0)*KST;
    const float* krow1 = k_sh + (ty*2+1)*KST;
    #pragma unroll 4
    for (int kk = 0; kk < DD; kk++) {
      float4 b0 = *(const float4*)(Msh + kk*64 + tx*8);
      float4 b1 = *(const float4*)(Msh + kk*64 + tx*8 + 4);
      ULL bb0 = ((const ULL*)&b0)[0], bb1 = ((const ULL*)&b0)[1];
      ULL bb2 = ((const ULL*)&b1)[0], bb3 = ((const ULL*)&b1)[1];
      float a0 = krow0[kk], a1 = krow1[kk];
      ULL aa0 = pk2(a0, a0), aa1 = pk2(a1, a1);
      fma2(acc[0][0], aa0, bb0); fma2(acc[0][1], aa0, bb1);
      fma2(acc[0][2], aa0, bb2); fma2(acc[0][3], aa0, bb3);
      fma2(acc[1][0], aa1, bb0); fma2(acc[1][1], aa1, bb1);
      fma2(acc[1][2], aa1, bb2); fma2(acc[1][3], aa1, bb3);
    }
    #pragma unroll
    for (int u = 0; u < 2; u++) {
      float4 q0 = *(const float4*)(q_t + (ty*2+u)*64 + tx*8);
      float4 q1 = *(const float4*)(q_t + (ty*2+u)*64 + tx*8 + 4);
      float c0,c1,c2,c3,c4,c5,c6,c7;
      upk2(acc[u][0], c0, c1); upk2(acc[u][1], c2, c3);
      upk2(acc[u][2], c4, c5); upk2(acc[u][3], c6, c7);
      float p = c0*q0.x + c1*q0.y + c2*q0.z + c3*q0.w
              + c4*q1.x + c5*q1.y + c6*q1.z + c7*q1.w;
      p += __shfl_xor_sync(0xffffffffu, p, 1);
      p += __shfl_xor_sync(0xffffffffu, p, 2);
      p += __shfl_xor_sync(0xffffffffu, p, 4);
      if (tx == 0) att_sh[ty*2+u] += p;   // unique row per (warp,ty,u) -> no race
    }
  }
  // --- remainder: cols 192..199 (8 cols), 2 threads per edge ---
  __syncthreads();
  for (int idx = tid; idx < DD*2; idx += 512) {
    int i = idx >> 1, p = idx & 1;
    *(float4*)(Msh + i*8 + p*4) = *(const float4*)(Mr + (size_t)i*DD + 192 + p*4);
  }
  for (int idx = tid; idx < ABM*2; idx += 512) {
    int e = idx >> 1, p = idx & 1;
    *(float4*)(q_t + e*8 + p*4) = *(const float4*)(Qbase + (size_t)es_dst[e]*DD + 192 + p*4);
  }
  __syncthreads();
  if (tid < 256) {
    int e = tid >> 1, half = tid & 1;
    ULL acc0 = pk2(0.f,0.f), acc1 = pk2(0.f,0.f);
    const float* krow = k_sh + e*KST;
    #pragma unroll 4
    for (int kk = 0; kk < DD; kk++) {
      float a = krow[kk];
      ULL aa = pk2(a, a);
      float4 mv = *(const float4*)(Msh + kk*8 + half*4);
      fma2(acc0, aa, ((const ULL*)&mv)[0]);
      fma2(acc1, aa, ((const ULL*)&mv)[1]);
    }
    float4 qv = *(const float4*)(q_t + e*8 + half*4);
    float s0,s1,s2,s3; upk2(acc0,s0,s1); upk2(acc1,s2,s3);
    float p = s0*qv.x + s1*qv.y + s2*qv.z + s3*qv.w;
    p += __shfl_xor_sync(0xffffffffu, p, 1);
    if (half == 0) att_sh[e] += p;
  }
  __syncthreads();
  if (tid < m) {
    float a = att_sh[tid];
    int e = es_eid[tid];
    g_att2[g_p2[e]] = a;    // write into dst-sorted order
    unsigned u = __float_as_uint(a);
    u = (u & 0x80000000u) ? ~u : (u | 0x80000000u);
    atomicMax(&g_maxu[es_dst[tid]], u);
  }
}

// ---------------- per-dst softmax + weighted V aggregation + S merge (no atomics) --------
__device__ __forceinline__ float decf(unsigned u) {
  return (u & 0x80000000u) ? __uint_as_float(u ^ 0x80000000u) : __uint_as_float(~u);
}
__global__ __launch_bounds__(128) void k_agg2() {
  int d = blockIdx.x;
  int beg = g_off2[d], end = g_off2[d+1];
  int t = threadIdx.x;   // t<100 active for 2 cols each
  float m = decf(g_maxu[d]);
  float denom = 0.f;
  float ax = 0.f, ay = 0.f;
  const float* Vbase = g_KQVS + (size_t)2*NN*DD;
  for (int i = beg; i < end; i++) {
    float ex = __expf(g_att2[i] - m);
    denom += ex;
    int s = g_src2[i];
    if (t < 100) {
      float2 v = *(const float2*)(Vbase + (size_t)s*DD + t*2);
      ax = fmaf(ex, v.x, ax);
      ay = fmaf(ex, v.y, ay);
    }
  }
  if (t < 100) {
    float inv = (1.f/3.f) / fmaxf(denom, 1e-30f);
    size_t off = (size_t)d*DD + t*2;
    const float* Sb = g_KQVS + (size_t)3*NN*DD;
    float2 sv = *(const float2*)(Sb + off);
    float2 o;
    o.x = sv.x*(1.f/3.f) + ax*inv;
    o.y = sv.y*(1.f/3.f) + ay*inv;
    *(float2*)(g_agg + off) = o;
  }
}

// ---------------- column stats ----------------
#define ST_ROWS 48
__global__ __launch_bounds__(256) void k_stats() {
  int c = threadIdx.x;
  int r0 = blockIdx.x*ST_ROWS;
  if (c >= DD) return;
  float s = 0.f, s2 = 0.f;
  int rmax = NN - r0; if (rmax > ST_ROWS) rmax = ST_ROWS;
  for (int lr = 0; lr < rmax; lr++) {
    float val = g_agg[(size_t)(r0+lr)*DD + c];
    s += val; s2 = fmaf(val, val, s2);
  }
  atomicAdd(&g_colsum[c], s);
  atomicAdd(&g_colsum2[c], s2);
}
__global__ void k_bnprep(const float* __restrict__ gamma, const float* __restrict__ beta) {
  int c = threadIdx.x;
  if (c < DD) {
    float mean = g_colsum[c] * (1.f/NN);
    float var  = g_colsum2[c] * (1.f/NN) - mean*mean;
    float sc = gamma[c] * rsqrtf(var + 1e-5f);
    g_scale[c] = sc;
    g_shift[c] = beta[c] - mean*sc;
  }
}
__global__ void k_bnout(float* __restrict__ out) {
  int idx = blockIdx.x*blockDim.x + threadIdx.x;
  if (idx < NN*DD) {
    int c = idx - (idx/DD)*DD;
    float y = g_agg[idx]*g_scale[c] + g_shift[c];
    float t;
    asm("tanh.approx.f32 %0, %1;" : "=f"(t) : "f"(y));
    out[idx] = t;
  }
}

// ---------------- r_out = r_feats @ wR^T + b ----------------
__global__ void k_rout(const float* __restrict__ rf, const float* __restrict__ wr,
                       const float* __restrict__ br, float* __restrict__ out) {
  __shared__ float xs[DD];
  int r = blockIdx.x;
  int tid = threadIdx.x;
  if (tid < DD) xs[tid] = rf[(size_t)r*DD + tid];
  __syncthreads();
  if (tid < DD) {
    float acc = br[tid];
    const float* wrow = wr + (size_t)tid*DD;
    for (int i = 0; i < DD; i++) acc = fmaf(xs[i], wrow[i], acc);
    out[(size_t)r*DD + tid] = acc;
  }
}

// ---------------- launcher ----------------
extern "C" void kernel_launch(void* const* d_in, const int* in_sizes, int n_in,
                              void* d_out, int out_size) {
  const float* n_in_feats = (const float*)d_in[0];
  const float* r_feats    = (const float*)d_in[1];
  const float* loop_rel   = (const float*)d_in[3];
  const float* rel_att    = (const float*)d_in[4];
  const float* w_comp     = (const float*)d_in[5];
  const float* wS_w = (const float*)d_in[10]; const float* wS_b = (const float*)d_in[11];
  const float* wR_w = (const float*)d_in[12]; const float* wR_b = (const float*)d_in[13];
  const float* k_w  = (const float*)d_in[14]; const float* k_b  = (const float*)d_in[15];
  const float* q_w  = (const float*)d_in[16]; const float* q_b  = (const float*)d_in[17];
  const float* v_w  = (const float*)d_in[18]; const float* v_b  = (const float*)d_in[19];
  const float* gamma = (const float*)d_in[20]; const float* beta = (const float*)d_in[21];
  const int* src   = (const int*)d_in[22];
  const int* dst   = (const int*)d_in[23];
  const int* etype = (const int*)d_in[24];
  float* out = (float*)d_out;

  cudaFuncSetAttribute(k_gemm, cudaFuncAttributeMaxDynamicSharedMemorySize, GEMM_SMEM);
  cudaFuncSetAttribute(k_att,  cudaFuncAttributeMaxDynamicSharedMemorySize, ATT_SMEM);

  k_packb<<<25, 256>>>(k_b, q_b, v_b, wS_b, loop_rel, wS_w);
  k_pack<<<(OUT4*DD + 255)/256, 256>>>(k_w, q_w, v_w, wS_w);
  {
    dim3 g((NN + 31)/32, (DD + 31)/32);
    k_transX<<<g, dim3(32, 8)>>>(n_in_feats);
  }
  {
    dim3 g((NN + GBM - 1)/GBM, (OUT4 + GBN - 1)/GBN);
    k_gemm<<<g, 256, GEMM_SMEM>>>();      // 4th launch -> ncu capture slot
  }
  k_init<<<256, 256>>>();
  k_compM<<<(DD*DD + 255)/256, 256>>>(rel_att, w_comp);
  k_hist<<<(EE+255)/256, 256>>>(etype, dst);
  k_scan<<<1, 32>>>();
  k_scan2<<<1, 1024>>>();
  k_scatter<<<(EE+255)/256, 256>>>(etype, src, dst);
  {
    dim3 g(RR, 16);
    k_att<<<g, 512, ATT_SMEM>>>(src, dst);
  }
  k_agg2<<<NN, 128>>>();
  k_stats<<<(NN + ST_ROWS - 1)/ST_ROWS, 256>>>();
  k_bnprep<<<1, 256>>>(gamma, beta);
  k_bnout<<<(NN*DD + 255)/256, 256>>>(out);
  k_rout<<<RR, 256>>>(r_feats, wR_w, wR_b, out + (size_t)NN*DD);
}

// round 10
// speedup vs baseline: 1.9331x; 1.2068x over previous
#include <cuda_runtime.h>
#include <cstdint>
#include <math.h>

#define NN 30000
#define EE 100000
#define DD 200
#define RR 100
#define BB 50
#define OUT4 (4*DD)   // 800 packed output columns: k,q,v,s

typedef unsigned long long ULL;

// ---------------- packed f32x2 helpers (FFMA2: 2x fp32 FMA throughput) ----------------
__device__ __forceinline__ ULL pk2(float a, float b) {
  ULL r; asm("mov.b64 %0,{%1,%2};" : "=l"(r) : "f"(a), "f"(b)); return r;
}
__device__ __forceinline__ void upk2(ULL d, float& x, float& y) {
  asm("mov.b64 {%0,%1},%2;" : "=f"(x), "=f"(y) : "l"(d));
}
__device__ __forceinline__ void fma2(ULL& d, ULL a, ULL b) {
  asm("fma.rn.f32x2 %0,%1,%2,%0;" : "+l"(d) : "l"(a), "l"(b));
}

// ---------------- scratch (static device globals; no runtime alloc) ----------------
__device__ __align__(16) float g_M[RR*DD*DD];        // per-relation matrices, 16MB
__device__ __align__(16) float g_W4T[DD*OUT4];       // packed weights, k-major [200][800]
__device__ __align__(16) float g_XT[DD*NN];          // transposed X, k-major [200][30000]
__device__ float g_b4[OUT4];
__device__ __align__(16) float g_KQVS[4u*NN*DD];     // K|Q|V|S node features, 96MB
__device__ unsigned g_maxu[NN];
__device__ __align__(16) float g_agg[NN*DD];         // n_pre (merged) output
__device__ int g_cnt[RR];
__device__ int g_off[RR+1];
__device__ int g_cur[RR];
__device__ int g_eid[EE];
__device__ int g_cnt2[NN];      // dst histogram
__device__ int g_off2[NN+1];
__device__ int g_cur2[NN];
__device__ int g_p2[EE];        // e -> dst-sorted position
__device__ int g_src2[EE];      // src, dst-sorted
__device__ float g_att2[EE];    // att, dst-sorted
__device__ float g_colsum[DD];
__device__ float g_colsum2[DD];
__device__ float g_scale[DD];
__device__ float g_shift[DD];

// ---------------- biases: k/q/v elementwise; S bias folds -(loop_rel @ wS^T) ----------------
__global__ void k_packb(const float* __restrict__ kb, const float* __restrict__ qb,
                        const float* __restrict__ vb, const float* __restrict__ sb,
                        const float* __restrict__ loop, const float* __restrict__ sw) {
  int tid = threadIdx.x, blk = blockIdx.x;
  int g = blk*256 + tid;
  if (g < 600) {
    int z = g / DD, j = g - z*DD;
    g_b4[g] = (z==0)?kb[j]:(z==1)?qb[j]:vb[j];
  }
  int w = blk*8 + (tid >> 5);
  int lane = tid & 31;
  if (w < DD) {
    float acc = 0.f;
    for (int i = lane; i < DD; i += 32) acc = fmaf(loop[i], sw[(size_t)w*DD + i], acc);
    #pragma unroll
    for (int o = 16; o; o >>= 1) acc += __shfl_xor_sync(0xffffffffu, acc, o);
    if (lane == 0) g_b4[600 + w] = sb[w] - acc;
  }
}

// ---------------- pack weights k-major: g_W4T[i][o] = w_z[j][i], o=z*DD+j ----------------
__global__ void k_pack(const float* __restrict__ kw, const float* __restrict__ qw,
                       const float* __restrict__ vw, const float* __restrict__ sw) {
  int idx = blockIdx.x*blockDim.x + threadIdx.x;
  if (idx >= OUT4*DD) return;
  int i = idx / OUT4, o = idx - i*OUT4;
  int z = o / DD, j = o - z*DD;
  const float* w = (z==0)?kw:(z==1)?qw:(z==2)?vw:sw;
  g_W4T[idx] = w[(size_t)j*DD + i];
}

// ---------------- transpose X [NN][DD] -> g_XT [DD][NN] ----------------
__global__ void k_transX(const float* __restrict__ X) {
  __shared__ float t[32][33];
  int bx = blockIdx.x*32;   // n base
  int by = blockIdx.y*32;   // d base
  int tx = threadIdx.x, ty = threadIdx.y;
  #pragma unroll
  for (int i = 0; i < 32; i += 8) {
    int n = bx + ty + i, d = by + tx;
    t[ty+i][tx] = (n < NN && d < DD) ? X[(size_t)n*DD + d] : 0.f;
  }
  __syncthreads();
  #pragma unroll
  for (int i = 0; i < 32; i += 8) {
    int d = by + ty + i, n = bx + tx;
    if (d < DD && n < NN) g_XT[(size_t)d*NN + n] = t[tx][ty+i];
  }
}

// ---------------- fused GEMM -> K,Q,V,S (f32x2, 2 k-phases, target 2 blocks/SM) --------
#define GBM 128
#define GBN 128
#define GBK 100
#define GSTG (GBK*GBM)            // 12800 floats per matrix
#define GEMM_SMEM (2*GSTG*4)      // 102400 B
__global__ __launch_bounds__(256, 2) void k_gemm() {
  extern __shared__ __align__(16) float sm[];
  float* As = sm;            // [100][128]
  float* Bs = sm + GSTG;     // [100][128]
  int row0 = blockIdx.x*GBM, col0 = blockIdx.y*GBN;
  int tid = threadIdx.x;

  // 4x2 warps, 4x8 lanes, 8x8 thread tile
  int w = tid >> 5, lane = tid & 31;
  int wm = w & 3, wn = w >> 2;
  int lm = lane >> 3, ln = lane & 7;
  int m0 = wm*32 + lm*8;
  int n0 = wn*64 + ln*8;

  ULL acc[8][4];
  #pragma unroll
  for (int u = 0; u < 8; u++)
    #pragma unroll
    for (int v = 0; v < 4; v++) acc[u][v] = pk2(0.f, 0.f);

  #pragma unroll
  for (int s = 0; s < 2; s++) {
    int k0 = s*GBK;
    __syncthreads();   // previous compute done before overwriting buffers
    // limited unroll keeps in-flight LDG register footprint small (reg budget = 128)
    #pragma unroll 4
    for (int l = 0; l < 13; l++) {
      int idx = tid + l*256;          // 3200 float4s per matrix
      if (idx < GSTG/4) {
        int r = idx >> 5, c = idx & 31;
        int gm = row0 + c*4;
        float4 f = make_float4(0.f,0.f,0.f,0.f);
        if (gm + 3 < NN) f = *(const float4*)(g_XT + (size_t)(k0+r)*NN + gm);
        *(float4*)&As[r*GBM + c*4] = f;
      }
    }
    #pragma unroll 4
    for (int l = 0; l < 13; l++) {
      int idx = tid + l*256;
      if (idx < GSTG/4) {
        int r = idx >> 5, c = idx & 31;
        int go = col0 + c*4;
        float4 f = make_float4(0.f,0.f,0.f,0.f);
        if (go + 3 < OUT4) f = *(const float4*)(g_W4T + (size_t)(k0+r)*OUT4 + go);
        *(float4*)&Bs[r*GBN + c*4] = f;
      }
    }
    __syncthreads();
    #pragma unroll 4
    for (int kk = 0; kk < GBK; kk++) {
      float4 a0 = *(const float4*)&As[kk*GBM + m0];
      float4 a1 = *(const float4*)&As[kk*GBM + m0 + 4];
      float4 b0 = *(const float4*)&Bs[kk*GBN + n0];
      float4 b1 = *(const float4*)&Bs[kk*GBN + n0 + 4];
      ULL bb[4];
      bb[0] = ((const ULL*)&b0)[0]; bb[1] = ((const ULL*)&b0)[1];
      bb[2] = ((const ULL*)&b1)[0]; bb[3] = ((const ULL*)&b1)[1];
      float av[8] = {a0.x,a0.y,a0.z,a0.w,a1.x,a1.y,a1.z,a1.w};
      #pragma unroll
      for (int u = 0; u < 8; u++) {
        ULL aa = pk2(av[u], av[u]);
        #pragma unroll
        for (int v = 0; v < 4; v++) fma2(acc[u][v], aa, bb[v]);
      }
    }
  }

  // epilogue: 8 rows x 8 cols per thread; cols never straddle a z-boundary (200%8==0)
  int o0 = col0 + n0;
  if (o0 < OUT4) {
    int z = o0 / DD, j0 = o0 - z*DD;
    float4 bi0 = *(const float4*)&g_b4[o0];
    float4 bi1 = *(const float4*)&g_b4[o0+4];
    float* outb = g_KQVS + (size_t)z*NN*DD + j0;
    #pragma unroll
    for (int u = 0; u < 8; u++) {
      int n = row0 + m0 + u;
      if (n >= NN) continue;
      float c0,c1,c2,c3,c4,c5,c6,c7;
      upk2(acc[u][0], c0, c1); upk2(acc[u][1], c2, c3);
      upk2(acc[u][2], c4, c5); upk2(acc[u][3], c6, c7);
      float4 s0 = make_float4(c0+bi0.x, c1+bi0.y, c2+bi0.z, c3+bi0.w);
      float4 s1 = make_float4(c4+bi1.x, c5+bi1.y, c6+bi1.z, c7+bi1.w);
      *(float4*)(outb + (size_t)n*DD)     = s0;
      *(float4*)(outb + (size_t)n*DD + 4) = s1;
    }
  }
}

// ---------------- init counters ----------------
__global__ void k_init() {
  int stride = gridDim.x*blockDim.x;
  int t0 = blockIdx.x*blockDim.x + threadIdx.x;
  for (int t = t0; t < NN; t += stride) {
    g_maxu[t] = 0x007FFFFFu;   // enc(-inf)
    g_cnt2[t] = 0; g_cur2[t] = 0;
  }
  for (int t = t0; t < RR; t += stride) { g_cnt[t] = 0; g_cur[t] = 0; }
  for (int t = t0; t < DD; t += stride) { g_colsum[t] = 0.f; g_colsum2[t] = 0.f; }
}

// ---------------- M_r = sum_b w_comp[r,b] * A_b  (register-cached) ----------------
__global__ __launch_bounds__(256) void k_compM(const float* __restrict__ A,
                                               const float* __restrict__ wc) {
  __shared__ float wsh[RR*BB];   // 20KB
  int tid = threadIdx.x;
  for (int idx = tid; idx < RR*BB; idx += 256) wsh[idx] = wc[idx];
  __syncthreads();
  int n = blockIdx.x*256 + tid;
  if (n >= DD*DD) return;
  float a[BB];
  #pragma unroll
  for (int b = 0; b < BB; b++) a[b] = A[(size_t)b*DD*DD + n];
  for (int r = 0; r < RR; r++) {
    float acc0 = 0.f, acc1 = 0.f;
    const float* wr = wsh + r*BB;
    #pragma unroll
    for (int b = 0; b < BB; b += 2) {
      acc0 = fmaf(wr[b],   a[b],   acc0);
      acc1 = fmaf(wr[b+1], a[b+1], acc1);
    }
    g_M[(size_t)r*DD*DD + n] = acc0 + acc1;
  }
}

// ---------------- histograms: by relation AND by dst ----------------
__global__ void k_hist(const int* __restrict__ et, const int* __restrict__ dst) {
  int e = blockIdx.x*blockDim.x + threadIdx.x;
  if (e < EE) {
    atomicAdd(&g_cnt[et[e]], 1);
    atomicAdd(&g_cnt2[dst[e]], 1);
  }
}
__global__ void k_scan() {
  if (threadIdx.x == 0) {
    int s = 0;
    for (int r = 0; r < RR; r++) { g_off[r] = s; s += g_cnt[r]; }
    g_off[RR] = s;
  }
}
// 1-block exclusive scan of g_cnt2[NN] -> g_off2
#define SC_CHUNK 30
__global__ __launch_bounds__(1024) void k_scan2() {
  __shared__ int ps[1024];
  int t = threadIdx.x;
  int base = t*SC_CHUNK;
  int s = 0;
  #pragma unroll
  for (int i = 0; i < SC_CHUNK; i++) { int idx = base+i; if (idx < NN) s += g_cnt2[idx]; }
  ps[t] = s;
  __syncthreads();
  for (int off = 1; off < 1024; off <<= 1) {
    int v = ps[t];
    int add = (t >= off) ? ps[t-off] : 0;
    __syncthreads();
    ps[t] = v + add;
    __syncthreads();
  }
  int run = (t > 0) ? ps[t-1] : 0;
  #pragma unroll
  for (int i = 0; i < SC_CHUNK; i++) {
    int idx = base+i;
    if (idx < NN) { g_off2[idx] = run; run += g_cnt2[idx]; }
  }
  if (t == 1023) g_off2[NN] = ps[1023];
}
__global__ void k_scatter(const int* __restrict__ et, const int* __restrict__ src,
                          const int* __restrict__ dst) {
  int e = blockIdx.x*blockDim.x + threadIdx.x;
  if (e < EE) {
    int t = et[e];
    int p = atomicAdd(&g_cur[t], 1);
    g_eid[g_off[t] + p] = e;
    int d = dst[e];
    int p2 = atomicAdd(&g_cur2[d], 1);
    int pos = g_off2[d] + p2;
    g_p2[e] = pos;
    g_src2[pos] = src[e];
  }
}

// ---------------- attention: att_e = k^T M_r q (f32x2), 256 thr, 4 rows/thread ----------
#define ABM 128
#define KST 204
#define ATT_SMEM ((ABM*KST + DD*64 + ABM*64 + ABM)*4 + 3*ABM*4)  // 190464 B
__global__ __launch_bounds__(256, 1) void k_att(const int* __restrict__ src,
                                                const int* __restrict__ dst) {
  extern __shared__ __align__(16) float sm[];
  float* k_sh   = sm;                 // [ABM][KST]
  float* Msh    = k_sh + ABM*KST;     // [DD][64] (reused as [DD][8] in remainder)
  float* q_t    = Msh + DD*64;        // [ABM][64] (reused as [ABM][8])
  float* att_sh = q_t + ABM*64;       // [ABM]
  int* es_src = (int*)(att_sh + ABM);
  int* es_dst = es_src + ABM;
  int* es_eid = es_dst + ABM;

  int r = blockIdx.x;
  int beg = g_off[r], end = g_off[r+1];
  int base = beg + blockIdx.y*ABM;
  if (base >= end) return;
  int m = end - base; if (m > ABM) m = ABM;
  int tid = threadIdx.x;
  if (tid < ABM) {
    int e = g_eid[base + ((tid < m) ? tid : 0)];
    es_eid[tid] = e;
    es_src[tid] = src[e];
    es_dst[tid] = dst[e];
    att_sh[tid] = 0.f;
  }
  __syncthreads();
  // gather K rows (float4) into padded smem
  for (int idx = tid; idx < ABM*(DD/4); idx += 256) {
    int e = idx / (DD/4), p = idx - e*(DD/4);
    *(float4*)(k_sh + e*KST + p*4) = *(const float4*)(g_KQVS + (size_t)es_src[e]*DD + p*4);
  }
  int tx = tid & 7;
  int ty = tid >> 3;        // 0..31, 4 rows each
  const float* Mr = g_M + (size_t)r*DD*DD;
  const float* Qbase = g_KQVS + (size_t)NN*DD;
  // --- 3 full 64-col tiles: cols 0..191 ---
  for (int jt = 0; jt < 3; jt++) {
    int j0 = jt*64;
    __syncthreads();
    for (int idx = tid; idx < DD*16; idx += 256) {
      int i = idx >> 4, p = idx & 15;
      *(float4*)(Msh + i*64 + p*4) = *(const float4*)(Mr + (size_t)i*DD + j0 + p*4);
    }
    for (int idx = tid; idx < ABM*16; idx += 256) {
      int e = idx >> 4, p = idx & 15;
      *(float4*)(q_t + e*64 + p*4) = *(const float4*)(Qbase + (size_t)es_dst[e]*DD + j0 + p*4);
    }
    __syncthreads();
    ULL acc[4][4];
    #pragma unroll
    for (int u = 0; u < 4; u++)
      #pragma unroll
      for (int v = 0; v < 4; v++) acc[u][v] = pk2(0.f, 0.f);
    #pragma unroll 4
    for (int kk = 0; kk < DD; kk++) {
      float4 b0 = *(const float4*)(Msh + kk*64 + tx*8);
      float4 b1 = *(const float4*)(Msh + kk*64 + tx*8 + 4);
      ULL bb0 = ((const ULL*)&b0)[0], bb1 = ((const ULL*)&b0)[1];
      ULL bb2 = ((const ULL*)&b1)[0], bb3 = ((const ULL*)&b1)[1];
      #pragma unroll
      for (int u = 0; u < 4; u++) {
        float a = k_sh[(ty*4+u)*KST + kk];
        ULL aa = pk2(a, a);
        fma2(acc[u][0], aa, bb0); fma2(acc[u][1], aa, bb1);
        fma2(acc[u][2], aa, bb2); fma2(acc[u][3], aa, bb3);
      }
    }
    #pragma unroll
    for (int u = 0; u < 4; u++) {
      float4 q0 = *(const float4*)(q_t + (ty*4+u)*64 + tx*8);
      float4 q1 = *(const float4*)(q_t + (ty*4+u)*64 + tx*8 + 4);
      float c0,c1,c2,c3,c4,c5,c6,c7;
      upk2(acc[u][0], c0, c1); upk2(acc[u][1], c2, c3);
      upk2(acc[u][2], c4, c5); upk2(acc[u][3], c6, c7);
      float p = c0*q0.x + c1*q0.y + c2*q0.z + c3*q0.w
              + c4*q1.x + c5*q1.y + c6*q1.z + c7*q1.w;
      p += __shfl_xor_sync(0xffffffffu, p, 1);
      p += __shfl_xor_sync(0xffffffffu, p, 2);
      p += __shfl_xor_sync(0xffffffffu, p, 4);
      if (tx == 0) att_sh[ty*4+u] += p;
    }
  }
  // --- remainder: cols 192..199 (8 cols), 2 threads per edge ---
  __syncthreads();
  for (int idx = tid; idx < DD*2; idx += 256) {
    int i = idx >> 1, p = idx & 1;
    *(float4*)(Msh + i*8 + p*4) = *(const float4*)(Mr + (size_t)i*DD + 192 + p*4);
  }
  for (int idx = tid; idx < ABM*2; idx += 256) {
    int e = idx >> 1, p = idx & 1;
    *(float4*)(q_t + e*8 + p*4) = *(const float4*)(Qbase + (size_t)es_dst[e]*DD + 192 + p*4);
  }
  __syncthreads();
  {
    int e = tid >> 1, half = tid & 1;
    ULL acc0 = pk2(0.f,0.f), acc1 = pk2(0.f,0.f);
    const float* krow = k_sh + e*KST;
    #pragma unroll 4
    for (int kk = 0; kk < DD; kk++) {
      float a = krow[kk];
      ULL aa = pk2(a, a);
      float4 mv = *(const float4*)(Msh + kk*8 + half*4);
      fma2(acc0, aa, ((const ULL*)&mv)[0]);
      fma2(acc1, aa, ((const ULL*)&mv)[1]);
    }
    float4 qv = *(const float4*)(q_t + e*8 + half*4);
    float s0,s1,s2,s3; upk2(acc0,s0,s1); upk2(acc1,s2,s3);
    float p = s0*qv.x + s1*qv.y + s2*qv.z + s3*qv.w;
    p += __shfl_xor_sync(0xffffffffu, p, 1);
    if (half == 0) att_sh[e] += p;
  }
  __syncthreads();
  if (tid < m) {
    float a = att_sh[tid];
    int e = es_eid[tid];
    g_att2[g_p2[e]] = a;    // write into dst-sorted order
    unsigned u = __float_as_uint(a);
    u = (u & 0x80000000u) ? ~u : (u | 0x80000000u);
    atomicMax(&g_maxu[es_dst[tid]], u);
  }
}

// ---------------- per-dst softmax + weighted V aggregation + S merge (no atomics) --------
__device__ __forceinline__ float decf(unsigned u) {
  return (u & 0x80000000u) ? __uint_as_float(u ^ 0x80000000u) : __uint_as_float(~u);
}
__global__ __launch_bounds__(128) void k_agg2() {
  int d = blockIdx.x;
  int beg = g_off2[d], end = g_off2[d+1];
  int t = threadIdx.x;   // t<100 active for 2 cols each
  float m = decf(g_maxu[d]);
  float denom = 0.f;
  float ax = 0.f, ay = 0.f;
  const float* Vbase = g_KQVS + (size_t)2*NN*DD;
  for (int i = beg; i < end; i++) {
    float ex = __expf(g_att2[i] - m);
    denom += ex;
    int s = g_src2[i];
    if (t < 100) {
      float2 v = *(const float2*)(Vbase + (size_t)s*DD + t*2);
      ax = fmaf(ex, v.x, ax);
      ay = fmaf(ex, v.y, ay);
    }
  }
  if (t < 100) {
    float inv = (1.f/3.f) / fmaxf(denom, 1e-30f);
    size_t off = (size_t)d*DD + t*2;
    const float* Sb = g_KQVS + (size_t)3*NN*DD;
    float2 sv = *(const float2*)(Sb + off);
    float2 o;
    o.x = sv.x*(1.f/3.f) + ax*inv;
    o.y = sv.y*(1.f/3.f) + ay*inv;
    *(float2*)(g_agg + off) = o;
  }
}

// ---------------- column stats ----------------
#define ST_ROWS 48
__global__ __launch_bounds__(256) void k_stats() {
  int c = threadIdx.x;
  int r0 = blockIdx.x*ST_ROWS;
  if (c >= DD) return;
  float s = 0.f, s2 = 0.f;
  int rmax = NN - r0; if (rmax > ST_ROWS) rmax = ST_ROWS;
  for (int lr = 0; lr < rmax; lr++) {
    float val = g_agg[(size_t)(r0+lr)*DD + c];
    s += val; s2 = fmaf(val, val, s2);
  }
  atomicAdd(&g_colsum[c], s);
  atomicAdd(&g_colsum2[c], s2);
}
__global__ void k_bnprep(const float* __restrict__ gamma, const float* __restrict__ beta) {
  int c = threadIdx.x;
  if (c < DD) {
    float mean = g_colsum[c] * (1.f/NN);
    float var  = g_colsum2[c] * (1.f/NN) - mean*mean;
    float sc = gamma[c] * rsqrtf(var + 1e-5f);
    g_scale[c] = sc;
    g_shift[c] = beta[c] - mean*sc;
  }
}
__global__ void k_bnout(float* __restrict__ out) {
  int idx = blockIdx.x*blockDim.x + threadIdx.x;
  if (idx < NN*DD) {
    int c = idx - (idx/DD)*DD;
    float y = g_agg[idx]*g_scale[c] + g_shift[c];
    float t;
    asm("tanh.approx.f32 %0, %1;" : "=f"(t) : "f"(y));
    out[idx] = t;
  }
}

// ---------------- r_out = r_feats @ wR^T + b ----------------
__global__ void k_rout(const float* __restrict__ rf, const float* __restrict__ wr,
                       const float* __restrict__ br, float* __restrict__ out) {
  __shared__ float xs[DD];
  int r = blockIdx.x;
  int tid = threadIdx.x;
  if (tid < DD) xs[tid] = rf[(size_t)r*DD + tid];
  __syncthreads();
  if (tid < DD) {
    float acc = br[tid];
    const float* wrow = wr + (size_t)tid*DD;
    for (int i = 0; i < DD; i++) acc = fmaf(xs[i], wrow[i], acc);
    out[(size_t)r*DD + tid] = acc;
  }
}

// ---------------- launcher ----------------
extern "C" void kernel_launch(void* const* d_in, const int* in_sizes, int n_in,
                              void* d_out, int out_size) {
  const float* n_in_feats = (const float*)d_in[0];
  const float* r_feats    = (const float*)d_in[1];
  const float* loop_rel   = (const float*)d_in[3];
  const float* rel_att    = (const float*)d_in[4];
  const float* w_comp     = (const float*)d_in[5];
  const float* wS_w = (const float*)d_in[10]; const float* wS_b = (const float*)d_in[11];
  const float* wR_w = (const float*)d_in[12]; const float* wR_b = (const float*)d_in[13];
  const float* k_w  = (const float*)d_in[14]; const float* k_b  = (const float*)d_in[15];
  const float* q_w  = (const float*)d_in[16]; const float* q_b  = (const float*)d_in[17];
  const float* v_w  = (const float*)d_in[18]; const float* v_b  = (const float*)d_in[19];
  const float* gamma = (const float*)d_in[20]; const float* beta = (const float*)d_in[21];
  const int* src   = (const int*)d_in[22];
  const int* dst   = (const int*)d_in[23];
  const int* etype = (const int*)d_in[24];
  float* out = (float*)d_out;

  cudaFuncSetAttribute(k_gemm, cudaFuncAttributeMaxDynamicSharedMemorySize, GEMM_SMEM);
  cudaFuncSetAttribute(k_att,  cudaFuncAttributeMaxDynamicSharedMemorySize, ATT_SMEM);

  k_packb<<<25, 256>>>(k_b, q_b, v_b, wS_b, loop_rel, wS_w);
  k_pack<<<(OUT4*DD + 255)/256, 256>>>(k_w, q_w, v_w, wS_w);
  {
    dim3 g((NN + 31)/32, (DD + 31)/32);
    k_transX<<<g, dim3(32, 8)>>>(n_in_feats);
  }
  {
    dim3 g((NN + GBM - 1)/GBM, (OUT4 + GBN - 1)/GBN);
    k_gemm<<<g, 256, GEMM_SMEM>>>();      // 4th launch -> ncu capture slot
  }
  k_init<<<256, 256>>>();
  k_compM<<<(DD*DD + 255)/256, 256>>>(rel_att, w_comp);
  k_hist<<<(EE+255)/256, 256>>>(etype, dst);
  k_scan<<<1, 32>>>();
  k_scan2<<<1, 1024>>>();
  k_scatter<<<(EE+255)/256, 256>>>(etype, src, dst);
  {
    dim3 g(RR, 16);
    k_att<<<g, 256, ATT_SMEM>>>(src, dst);
  }
  k_agg2<<<NN, 128>>>();
  k_stats<<<(NN + ST_ROWS - 1)/ST_ROWS, 256>>>();
  k_bnprep<<<1, 256>>>(gamma, beta);
  k_bnout<<<(NN*DD + 255)/256, 256>>>(out);
  k_rout<<<RR, 256>>>(r_feats, wR_w, wR_b, out + (size_t)NN*DD);
}

// round 12
// speedup vs baseline: 1.9413x; 1.0042x over previous
#include <cuda_runtime.h>
#include <cstdint>
#include <math.h>

#define NN 30000
#define EE 100000
#define DD 200
#define RR 100
#define BB 50
#define OUT4 (4*DD)   // 800 packed output columns: k,q,v,s

typedef unsigned long long ULL;

// ---------------- packed f32x2 helpers (FFMA2: 2x fp32 FMA throughput) ----------------
__device__ __forceinline__ ULL pk2(float a, float b) {
  ULL r; asm("mov.b64 %0,{%1,%2};" : "=l"(r) : "f"(a), "f"(b)); return r;
}
__device__ __forceinline__ void upk2(ULL d, float& x, float& y) {
  asm("mov.b64 {%0,%1},%2;" : "=f"(x), "=f"(y) : "l"(d));
}
__device__ __forceinline__ void fma2(ULL& d, ULL a, ULL b) {
  asm("fma.rn.f32x2 %0,%1,%2,%0;" : "+l"(d) : "l"(a), "l"(b));
}

// ---------------- scratch (static device globals; no runtime alloc) ----------------
__device__ __align__(16) float g_M[RR*DD*DD];        // per-relation matrices, 16MB
__device__ __align__(16) float g_W4T[DD*OUT4];       // packed weights, k-major [200][800]
__device__ __align__(16) float g_XT[DD*NN];          // transposed X, k-major [200][30000]
__device__ float g_b4[OUT4];
__device__ __align__(16) float g_KQVS[4u*NN*DD];     // K|Q|V|S node features, 96MB
__device__ unsigned g_maxu[NN];
__device__ __align__(16) float g_agg[NN*DD];         // n_pre (merged) output
__device__ int g_cnt[RR];
__device__ int g_off[RR+1];
__device__ int g_cur[RR];
__device__ int g_eid[EE];
__device__ int g_cnt2[NN];      // dst histogram
__device__ int g_off2[NN+1];
__device__ int g_cur2[NN];
__device__ int g_p2[EE];        // e -> dst-sorted position
__device__ int g_src2[EE];      // src, dst-sorted
__device__ float g_att2[EE];    // att, dst-sorted
__device__ float g_colsum[DD];
__device__ float g_colsum2[DD];
__device__ float g_scale[DD];
__device__ float g_shift[DD];

// ---------------- biases: k/q/v elementwise; S bias folds -(loop_rel @ wS^T) ----------------
__global__ void k_packb(const float* __restrict__ kb, const float* __restrict__ qb,
                        const float* __restrict__ vb, const float* __restrict__ sb,
                        const float* __restrict__ loop, const float* __restrict__ sw) {
  int tid = threadIdx.x, blk = blockIdx.x;
  int g = blk*256 + tid;
  if (g < 600) {
    int z = g / DD, j = g - z*DD;
    g_b4[g] = (z==0)?kb[j]:(z==1)?qb[j]:vb[j];
  }
  int w = blk*8 + (tid >> 5);
  int lane = tid & 31;
  if (w < DD) {
    float acc = 0.f;
    for (int i = lane; i < DD; i += 32) acc = fmaf(loop[i], sw[(size_t)w*DD + i], acc);
    #pragma unroll
    for (int o = 16; o; o >>= 1) acc += __shfl_xor_sync(0xffffffffu, acc, o);
    if (lane == 0) g_b4[600 + w] = sb[w] - acc;
  }
}

// ---------------- pack weights k-major: g_W4T[i][o] = w_z[j][i], o=z*DD+j ----------------
__global__ void k_pack(const float* __restrict__ kw, const float* __restrict__ qw,
                       const float* __restrict__ vw, const float* __restrict__ sw) {
  int idx = blockIdx.x*blockDim.x + threadIdx.x;
  if (idx >= OUT4*DD) return;
  int i = idx / OUT4, o = idx - i*OUT4;
  int z = o / DD, j = o - z*DD;
  const float* w = (z==0)?kw:(z==1)?qw:(z==2)?vw:sw;
  g_W4T[idx] = w[(size_t)j*DD + i];
}

// ---------------- transpose X [NN][DD] -> g_XT [DD][NN] ----------------
__global__ void k_transX(const float* __restrict__ X) {
  __shared__ float t[32][33];
  int bx = blockIdx.x*32;   // n base
  int by = blockIdx.y*32;   // d base
  int tx = threadIdx.x, ty = threadIdx.y;
  #pragma unroll
  for (int i = 0; i < 32; i += 8) {
    int n = bx + ty + i, d = by + tx;
    t[ty+i][tx] = (n < NN && d < DD) ? X[(size_t)n*DD + d] : 0.f;
  }
  __syncthreads();
  #pragma unroll
  for (int i = 0; i < 32; i += 8) {
    int d = by + ty + i, n = bx + tx;
    if (d < DD && n < NN) g_XT[(size_t)d*NN + n] = t[tx][ty+i];
  }
}

// ---------------- fused GEMM -> K,Q,V,S (f32x2, 2 k-phases; round-9 best config) ------
#define GBM 128
#define GBN 128
#define GBK 100
#define GSTG (GBK*GBM)            // 12800 floats per matrix
#define GEMM_SMEM (2*GSTG*4)      // 102400 B
__global__ __launch_bounds__(256) void k_gemm() {
  extern __shared__ __align__(16) float sm[];
  float* As = sm;            // [100][128]
  float* Bs = sm + GSTG;     // [100][128]
  int row0 = blockIdx.x*GBM, col0 = blockIdx.y*GBN;
  int tid = threadIdx.x;

  // 4x2 warps, 4x8 lanes, 8x8 thread tile
  int w = tid >> 5, lane = tid & 31;
  int wm = w & 3, wn = w >> 2;
  int lm = lane >> 3, ln = lane & 7;
  int m0 = wm*32 + lm*8;
  int n0 = wn*64 + ln*8;

  ULL acc[8][4];
  #pragma unroll
  for (int u = 0; u < 8; u++)
    #pragma unroll
    for (int v = 0; v < 4; v++) acc[u][v] = pk2(0.f, 0.f);

  #pragma unroll
  for (int s = 0; s < 2; s++) {
    int k0 = s*GBK;
    __syncthreads();   // previous compute done before overwriting buffers
    #pragma unroll
    for (int l = 0; l < 13; l++) {
      int idx = tid + l*256;          // 3200 float4s per matrix
      if (idx < GSTG/4) {
        int r = idx >> 5, c = idx & 31;
        int gm = row0 + c*4;
        float4 f = make_float4(0.f,0.f,0.f,0.f);
        if (gm + 3 < NN) f = *(const float4*)(g_XT + (size_t)(k0+r)*NN + gm);
        *(float4*)&As[r*GBM + c*4] = f;
      }
    }
    #pragma unroll
    for (int l = 0; l < 13; l++) {
      int idx = tid + l*256;
      if (idx < GSTG/4) {
        int r = idx >> 5, c = idx & 31;
        int go = col0 + c*4;
        float4 f = make_float4(0.f,0.f,0.f,0.f);
        if (go + 3 < OUT4) f = *(const float4*)(g_W4T + (size_t)(k0+r)*OUT4 + go);
        *(float4*)&Bs[r*GBN + c*4] = f;
      }
    }
    __syncthreads();
    #pragma unroll 4
    for (int kk = 0; kk < GBK; kk++) {
      float4 a0 = *(const float4*)&As[kk*GBM + m0];
      float4 a1 = *(const float4*)&As[kk*GBM + m0 + 4];
      float4 b0 = *(const float4*)&Bs[kk*GBN + n0];
      float4 b1 = *(const float4*)&Bs[kk*GBN + n0 + 4];
      ULL bb[4];
      bb[0] = ((const ULL*)&b0)[0]; bb[1] = ((const ULL*)&b0)[1];
      bb[2] = ((const ULL*)&b1)[0]; bb[3] = ((const ULL*)&b1)[1];
      float av[8] = {a0.x,a0.y,a0.z,a0.w,a1.x,a1.y,a1.z,a1.w};
      #pragma unroll
      for (int u = 0; u < 8; u++) {
        ULL aa = pk2(av[u], av[u]);
        #pragma unroll
        for (int v = 0; v < 4; v++) fma2(acc[u][v], aa, bb[v]);
      }
    }
  }

  // epilogue: 8 rows x 8 cols per thread; cols never straddle a z-boundary (200%8==0)
  int o0 = col0 + n0;
  if (o0 < OUT4) {
    int z = o0 / DD, j0 = o0 - z*DD;
    float4 bi0 = *(const float4*)&g_b4[o0];
    float4 bi1 = *(const float4*)&g_b4[o0+4];
    float* outb = g_KQVS + (size_t)z*NN*DD + j0;
    #pragma unroll
    for (int u = 0; u < 8; u++) {
      int n = row0 + m0 + u;
      if (n >= NN) continue;
      float c0,c1,c2,c3,c4,c5,c6,c7;
      upk2(acc[u][0], c0, c1); upk2(acc[u][1], c2, c3);
      upk2(acc[u][2], c4, c5); upk2(acc[u][3], c6, c7);
      float4 s0 = make_float4(c0+bi0.x, c1+bi0.y, c2+bi0.z, c3+bi0.w);
      float4 s1 = make_float4(c4+bi1.x, c5+bi1.y, c6+bi1.z, c7+bi1.w);
      *(float4*)(outb + (size_t)n*DD)     = s0;
      *(float4*)(outb + (size_t)n*DD + 4) = s1;
    }
  }
}

// ---------------- init counters ----------------
__global__ void k_init() {
  int stride = gridDim.x*blockDim.x;
  int t0 = blockIdx.x*blockDim.x + threadIdx.x;
  for (int t = t0; t < NN; t += stride) {
    g_maxu[t] = 0x007FFFFFu;   // enc(-inf)
    g_cnt2[t] = 0; g_cur2[t] = 0;
  }
  for (int t = t0; t < RR; t += stride) { g_cnt[t] = 0; g_cur[t] = 0; }
  for (int t = t0; t < DD; t += stride) { g_colsum[t] = 0.f; g_colsum2[t] = 0.f; }
}

// ---------------- M_r = sum_b w_comp[r,b] * A_b  (register-cached) ----------------
__global__ __launch_bounds__(256) void k_compM(const float* __restrict__ A,
                                               const float* __restrict__ wc) {
  __shared__ float wsh[RR*BB];   // 20KB
  int tid = threadIdx.x;
  for (int idx = tid; idx < RR*BB; idx += 256) wsh[idx] = wc[idx];
  __syncthreads();
  int n = blockIdx.x*256 + tid;
  if (n >= DD*DD) return;
  float a[BB];
  #pragma unroll
  for (int b = 0; b < BB; b++) a[b] = A[(size_t)b*DD*DD + n];
  for (int r = 0; r < RR; r++) {
    float acc0 = 0.f, acc1 = 0.f;
    const float* wr = wsh + r*BB;
    #pragma unroll
    for (int b = 0; b < BB; b += 2) {
      acc0 = fmaf(wr[b],   a[b],   acc0);
      acc1 = fmaf(wr[b+1], a[b+1], acc1);
    }
    g_M[(size_t)r*DD*DD + n] = acc0 + acc1;
  }
}

// ---------------- histograms: by relation AND by dst ----------------
__global__ void k_hist(const int* __restrict__ et, const int* __restrict__ dst) {
  int e = blockIdx.x*blockDim.x + threadIdx.x;
  if (e < EE) {
    atomicAdd(&g_cnt[et[e]], 1);
    atomicAdd(&g_cnt2[dst[e]], 1);
  }
}
__global__ void k_scan() {
  if (threadIdx.x == 0) {
    int s = 0;
    for (int r = 0; r < RR; r++) { g_off[r] = s; s += g_cnt[r]; }
    g_off[RR] = s;
  }
}
// 1-block exclusive scan of g_cnt2[NN] -> g_off2
#define SC_CHUNK 30
__global__ __launch_bounds__(1024) void k_scan2() {
  __shared__ int ps[1024];
  int t = threadIdx.x;
  int base = t*SC_CHUNK;
  int s = 0;
  #pragma unroll
  for (int i = 0; i < SC_CHUNK; i++) { int idx = base+i; if (idx < NN) s += g_cnt2[idx]; }
  ps[t] = s;
  __syncthreads();
  for (int off = 1; off < 1024; off <<= 1) {
    int v = ps[t];
    int add = (t >= off) ? ps[t-off] : 0;
    __syncthreads();
    ps[t] = v + add;
    __syncthreads();
  }
  int run = (t > 0) ? ps[t-1] : 0;
  #pragma unroll
  for (int i = 0; i < SC_CHUNK; i++) {
    int idx = base+i;
    if (idx < NN) { g_off2[idx] = run; run += g_cnt2[idx]; }
  }
  if (t == 1023) g_off2[NN] = ps[1023];
}
__global__ void k_scatter(const int* __restrict__ et, const int* __restrict__ src,
                          const int* __restrict__ dst) {
  int e = blockIdx.x*blockDim.x + threadIdx.x;
  if (e < EE) {
    int t = et[e];
    int p = atomicAdd(&g_cur[t], 1);
    g_eid[g_off[t] + p] = e;
    int d = dst[e];
    int p2 = atomicAdd(&g_cur2[d], 1);
    int pos = g_off2[d] + p2;
    g_p2[e] = pos;
    g_src2[pos] = src[e];
  }
}

// ---------------- attention: att_e = k^T M_r q (f32x2), 256 thr, 4 rows/thread ----------
#define ABM 128
#define KST 204
#define ATT_SMEM ((ABM*KST + DD*64 + ABM*64 + ABM)*4 + 3*ABM*4)  // 190464 B
__global__ __launch_bounds__(256, 1) void k_att(const int* __restrict__ src,
                                                const int* __restrict__ dst) {
  extern __shared__ __align__(16) float sm[];
  float* k_sh   = sm;                 // [ABM][KST]
  float* Msh    = k_sh + ABM*KST;     // [DD][64] (reused as [DD][8] in remainder)
  float* q_t    = Msh + DD*64;        // [ABM][64] (reused as [ABM][8])
  float* att_sh = q_t + ABM*64;       // [ABM]
  int* es_src = (int*)(att_sh + ABM);
  int* es_dst = es_src + ABM;
  int* es_eid = es_dst + ABM;

  int r = blockIdx.x;
  int beg = g_off[r], end = g_off[r+1];
  int base = beg + blockIdx.y*ABM;
  if (base >= end) return;
  int m = end - base; if (m > ABM) m = ABM;
  int tid = threadIdx.x;
  if (tid < ABM) {
    int e = g_eid[base + ((tid < m) ? tid : 0)];
    es_eid[tid] = e;
    es_src[tid] = src[e];
    es_dst[tid] = dst[e];
    att_sh[tid] = 0.f;
  }
  __syncthreads();
  // gather K rows (float4) into padded smem
  for (int idx = tid; idx < ABM*(DD/4); idx += 256) {
    int e = idx / (DD/4), p = idx - e*(DD/4);
    *(float4*)(k_sh + e*KST + p*4) = *(const float4*)(g_KQVS + (size_t)es_src[e]*DD + p*4);
  }
  int tx = tid & 7;
  int ty = tid >> 3;        // 0..31, 4 rows each
  const float* Mr = g_M + (size_t)r*DD*DD;
  const float* Qbase = g_KQVS + (size_t)NN*DD;
  // --- 3 full 64-col tiles: cols 0..191 ---
  for (int jt = 0; jt < 3; jt++) {
    int j0 = jt*64;
    __syncthreads();
    for (int idx = tid; idx < DD*16; idx += 256) {
      int i = idx >> 4, p = idx & 15;
      *(float4*)(Msh + i*64 + p*4) = *(const float4*)(Mr + (size_t)i*DD + j0 + p*4);
    }
    for (int idx = tid; idx < ABM*16; idx += 256) {
      int e = idx >> 4, p = idx & 15;
      *(float4*)(q_t + e*64 + p*4) = *(const float4*)(Qbase + (size_t)es_dst[e]*DD + j0 + p*4);
    }
    __syncthreads();
    ULL acc[4][4];
    #pragma unroll
    for (int u = 0; u < 4; u++)
      #pragma unroll
      for (int v = 0; v < 4; v++) acc[u][v] = pk2(0.f, 0.f);
    #pragma unroll 4
    for (int kk = 0; kk < DD; kk++) {
      float4 b0 = *(const float4*)(Msh + kk*64 + tx*8);
      float4 b1 = *(const float4*)(Msh + kk*64 + tx*8 + 4);
      ULL bb0 = ((const ULL*)&b0)[0], bb1 = ((const ULL*)&b0)[1];
      ULL bb2 = ((const ULL*)&b1)[0], bb3 = ((const ULL*)&b1)[1];
      #pragma unroll
      for (int u = 0; u < 4; u++) {
        float a = k_sh[(ty*4+u)*KST + kk];
        ULL aa = pk2(a, a);
        fma2(acc[u][0], aa, bb0); fma2(acc[u][1], aa, bb1);
        fma2(acc[u][2], aa, bb2); fma2(acc[u][3], aa, bb3);
      }
    }
    #pragma unroll
    for (int u = 0; u < 4; u++) {
      float4 q0 = *(const float4*)(q_t + (ty*4+u)*64 + tx*8);
      float4 q1 = *(const float4*)(q_t + (ty*4+u)*64 + tx*8 + 4);
      float c0,c1,c2,c3,c4,c5,c6,c7;
      upk2(acc[u][0], c0, c1); upk2(acc[u][1], c2, c3);
      upk2(acc[u][2], c4, c5); upk2(acc[u][3], c6, c7);
      float p = c0*q0.x + c1*q0.y + c2*q0.z + c3*q0.w
              + c4*q1.x + c5*q1.y + c6*q1.z + c7*q1.w;
      p += __shfl_xor_sync(0xffffffffu, p, 1);
      p += __shfl_xor_sync(0xffffffffu, p, 2);
      p += __shfl_xor_sync(0xffffffffu, p, 4);
      if (tx == 0) att_sh[ty*4+u] += p;
    }
  }
  // --- remainder: cols 192..199 (8 cols), 2 threads per edge ---
  __syncthreads();
  for (int idx = tid; idx < DD*2; idx += 256) {
    int i = idx >> 1, p = idx & 1;
    *(float4*)(Msh + i*8 + p*4) = *(const float4*)(Mr + (size_t)i*DD + 192 + p*4);
  }
  for (int idx = tid; idx < ABM*2; idx += 256) {
    int e = idx >> 1, p = idx & 1;
    *(float4*)(q_t + e*8 + p*4) = *(const float4*)(Qbase + (size_t)es_dst[e]*DD + 192 + p*4);
  }
  __syncthreads();
  {
    int e = tid >> 1, half = tid & 1;
    ULL acc0 = pk2(0.f,0.f), acc1 = pk2(0.f,0.f);
    const float* krow = k_sh + e*KST;
    #pragma unroll 4
    for (int kk = 0; kk < DD; kk++) {
      float a = krow[kk];
      ULL aa = pk2(a, a);
      float4 mv = *(const float4*)(Msh + kk*8 + half*4);
      fma2(acc0, aa, ((const ULL*)&mv)[0]);
      fma2(acc1, aa, ((const ULL*)&mv)[1]);
    }
    float4 qv = *(const float4*)(q_t + e*8 + half*4);
    float s0,s1,s2,s3; upk2(acc0,s0,s1); upk2(acc1,s2,s3);
    float p = s0*qv.x + s1*qv.y + s2*qv.z + s3*qv.w;
    p += __shfl_xor_sync(0xffffffffu, p, 1);
    if (half == 0) att_sh[e] += p;
  }
  __syncthreads();
  if (tid < m) {
    float a = att_sh[tid];
    int e = es_eid[tid];
    g_att2[g_p2[e]] = a;    // write into dst-sorted order
    unsigned u = __float_as_uint(a);
    u = (u & 0x80000000u) ? ~u : (u | 0x80000000u);
    atomicMax(&g_maxu[es_dst[tid]], u);
  }
}

// ---------------- per-dst softmax + weighted V aggregation + S merge (no atomics) --------
__device__ __forceinline__ float decf(unsigned u) {
  return (u & 0x80000000u) ? __uint_as_float(u ^ 0x80000000u) : __uint_as_float(~u);
}
__global__ __launch_bounds__(128) void k_agg2() {
  int d = blockIdx.x;
  int beg = g_off2[d], end = g_off2[d+1];
  int t = threadIdx.x;   // t<100 active for 2 cols each
  float m = decf(g_maxu[d]);
  float denom = 0.f;
  float ax = 0.f, ay = 0.f;
  const float* Vbase = g_KQVS + (size_t)2*NN*DD;
  if (beg < end) {
    float a_cur = g_att2[beg];
    int   s_cur = g_src2[beg];
    for (int i = beg; i < end; i++) {
      float a_nxt = 0.f; int s_nxt = 0;
      if (i + 1 < end) { a_nxt = g_att2[i+1]; s_nxt = g_src2[i+1]; }  // prefetch
      float ex = __expf(a_cur - m);
      denom += ex;
      if (t < 100) {
        float2 v = *(const float2*)(Vbase + (size_t)s_cur*DD + t*2);
        ax = fmaf(ex, v.x, ax);
        ay = fmaf(ex, v.y, ay);
      }
      a_cur = a_nxt; s_cur = s_nxt;
    }
  }
  if (t < 100) {
    float inv = (1.f/3.f) / fmaxf(denom, 1e-30f);
    size_t off = (size_t)d*DD + t*2;
    const float* Sb = g_KQVS + (size_t)3*NN*DD;
    float2 sv = *(const float2*)(Sb + off);
    float2 o;
    o.x = sv.x*(1.f/3.f) + ax*inv;
    o.y = sv.y*(1.f/3.f) + ay*inv;
    *(float2*)(g_agg + off) = o;
  }
}

// ---------------- column stats ----------------
#define ST_ROWS 48
__global__ __launch_bounds__(256) void k_stats() {
  int c = threadIdx.x;
  int r0 = blockIdx.x*ST_ROWS;
  if (c >= DD) return;
  float s = 0.f, s2 = 0.f;
  int rmax = NN - r0; if (rmax > ST_ROWS) rmax = ST_ROWS;
  for (int lr = 0; lr < rmax; lr++) {
    float val = g_agg[(size_t)(r0+lr)*DD + c];
    s += val; s2 = fmaf(val, val, s2);
  }
  atomicAdd(&g_colsum[c], s);
  atomicAdd(&g_colsum2[c], s2);
}
__global__ void k_bnprep(const float* __restrict__ gamma, const float* __restrict__ beta) {
  int c = threadIdx.x;
  if (c < DD) {
    float mean = g_colsum[c] * (1.f/NN);
    float var  = g_colsum2[c] * (1.f/NN) - mean*mean;
    float sc = gamma[c] * rsqrtf(var + 1e-5f);
    g_scale[c] = sc;
    g_shift[c] = beta[c] - mean*sc;
  }
}
__global__ void k_bnout(float* __restrict__ out) {
  int idx = blockIdx.x*blockDim.x + threadIdx.x;
  if (idx < NN*DD) {
    int c = idx - (idx/DD)*DD;
    float y = g_agg[idx]*g_scale[c] + g_shift[c];
    float t;
    asm("tanh.approx.f32 %0, %1;" : "=f"(t) : "f"(y));
    out[idx] = t;
  }
}

// ---------------- r_out = r_feats @ wR^T + b ----------------
__global__ void k_rout(const float* __restrict__ rf, const float* __restrict__ wr,
                       const float* __restrict__ br, float* __restrict__ out) {
  __shared__ float xs[DD];
  int r = blockIdx.x;
  int tid = threadIdx.x;
  if (tid < DD) xs[tid] = rf[(size_t)r*DD + tid];
  __syncthreads();
  if (tid < DD) {
    float acc = br[tid];
    const float* wrow = wr + (size_t)tid*DD;
    for (int i = 0; i < DD; i++) acc = fmaf(xs[i], wrow[i], acc);
    out[(size_t)r*DD + tid] = acc;
  }
}

// ---------------- launcher ----------------
extern "C" void kernel_launch(void* const* d_in, const int* in_sizes, int n_in,
                              void* d_out, int out_size) {
  const float* n_in_feats = (const float*)d_in[0];
  const float* r_feats    = (const float*)d_in[1];
  const float* loop_rel   = (const float*)d_in[3];
  const float* rel_att    = (const float*)d_in[4];
  const float* w_comp     = (const float*)d_in[5];
  const float* wS_w = (const float*)d_in[10]; const float* wS_b = (const float*)d_in[11];
  const float* wR_w = (const float*)d_in[12]; const float* wR_b = (const float*)d_in[13];
  const float* k_w  = (const float*)d_in[14]; const float* k_b  = (const float*)d_in[15];
  const float* q_w  = (const float*)d_in[16]; const float* q_b  = (const float*)d_in[17];
  const float* v_w  = (const float*)d_in[18]; const float* v_b  = (const float*)d_in[19];
  const float* gamma = (const float*)d_in[20]; const float* beta = (const float*)d_in[21];
  const int* src   = (const int*)d_in[22];
  const int* dst   = (const int*)d_in[23];
  const int* etype = (const int*)d_in[24];
  float* out = (float*)d_out;

  cudaFuncSetAttribute(k_gemm, cudaFuncAttributeMaxDynamicSharedMemorySize, GEMM_SMEM);
  cudaFuncSetAttribute(k_att,  cudaFuncAttributeMaxDynamicSharedMemorySize, ATT_SMEM);

  k_packb<<<25, 256>>>(k_b, q_b, v_b, wS_b, loop_rel, wS_w);
  k_pack<<<(OUT4*DD + 255)/256, 256>>>(k_w, q_w, v_w, wS_w);
  {
    dim3 g((NN + 31)/32, (DD + 31)/32);
    k_transX<<<g, dim3(32, 8)>>>(n_in_feats);
  }
  {
    dim3 g((NN + GBM - 1)/GBM, (OUT4 + GBN - 1)/GBN);
    k_gemm<<<g, 256, GEMM_SMEM>>>();      // 4th launch -> ncu capture slot
  }
  k_init<<<256, 256>>>();
  k_compM<<<(DD*DD + 255)/256, 256>>>(rel_att, w_comp);
  k_hist<<<(EE+255)/256, 256>>>(etype, dst);
  k_scan<<<1, 32>>>();
  k_scan2<<<1, 1024>>>();
  k_scatter<<<(EE+255)/256, 256>>>(etype, src, dst);
  {
    dim3 g(RR, 16);
    k_att<<<g, 256, ATT_SMEM>>>(src, dst);
  }
  k_agg2<<<NN, 128>>>();
  k_stats<<<(NN + ST_ROWS - 1)/ST_ROWS, 256>>>();
  k_bnprep<<<1, 256>>>(gamma, beta);
  k_bnout<<<(NN*DD + 255)/256, 256>>>(out);
  k_rout<<<RR, 256>>>(r_feats, wR_w, wR_b, out + (size_t)NN*DD);
}

// round 14
// speedup vs baseline: 1.9559x; 1.0075x over previous
#include <cuda_runtime.h>
#include <cstdint>
#include <math.h>

#define NN 30000
#define EE 100000
#define DD 200
#define RR 100
#define BB 50
#define OUT4 (4*DD)   // 800 packed output columns: k,q,v,s

typedef unsigned long long ULL;

// ---------------- packed f32x2 helpers (FFMA2: 2x fp32 FMA throughput) ----------------
__device__ __forceinline__ ULL pk2(float a, float b) {
  ULL r; asm("mov.b64 %0,{%1,%2};" : "=l"(r) : "f"(a), "f"(b)); return r;
}
__device__ __forceinline__ void upk2(ULL d, float& x, float& y) {
  asm("mov.b64 {%0,%1},%2;" : "=f"(x), "=f"(y) : "l"(d));
}
__device__ __forceinline__ void fma2(ULL& d, ULL a, ULL b) {
  asm("fma.rn.f32x2 %0,%1,%2,%0;" : "+l"(d) : "l"(a), "l"(b));
}

// ---------------- scratch (static device globals; no runtime alloc) ----------------
__device__ __align__(16) float g_M[RR*DD*DD];        // per-relation matrices, 16MB
__device__ __align__(16) float g_W4T[DD*OUT4];       // packed weights, k-major [200][800]
__device__ __align__(16) float g_XT[DD*NN];          // transposed X, k-major [200][30000]
__device__ __align__(16) float g_WRT[DD*DD];         // transposed wR, k-major [200][200]
__device__ float g_b4[OUT4];
__device__ __align__(16) float g_KQVS[4u*NN*DD];     // K|Q|V|S node features, 96MB
__device__ unsigned g_maxu[NN];
__device__ __align__(16) float g_agg[NN*DD];         // n_pre (merged) output
__device__ int g_cnt[RR];
__device__ int g_off[RR+1];
__device__ int g_cur[RR];
__device__ int g_eid[EE];
__device__ int g_cnt2[NN];      // dst histogram
__device__ int g_off2[NN+1];
__device__ int g_cur2[NN];
__device__ int g_p2[EE];        // e -> dst-sorted position
__device__ int g_src2[EE];      // src, dst-sorted
__device__ float g_att2[EE];    // att, dst-sorted
__device__ float g_colsum[DD];
__device__ float g_colsum2[DD];
__device__ float g_scale[DD];
__device__ float g_shift[DD];

// ---------------- biases: k/q/v elementwise; S bias folds -(loop_rel @ wS^T) ----------------
__global__ void k_packb(const float* __restrict__ kb, const float* __restrict__ qb,
                        const float* __restrict__ vb, const float* __restrict__ sb,
                        const float* __restrict__ loop, const float* __restrict__ sw) {
  int tid = threadIdx.x, blk = blockIdx.x;
  int g = blk*256 + tid;
  if (g < 600) {
    int z = g / DD, j = g - z*DD;
    g_b4[g] = (z==0)?kb[j]:(z==1)?qb[j]:vb[j];
  }
  int w = blk*8 + (tid >> 5);
  int lane = tid & 31;
  if (w < DD) {
    float acc = 0.f;
    for (int i = lane; i < DD; i += 32) acc = fmaf(loop[i], sw[(size_t)w*DD + i], acc);
    #pragma unroll
    for (int o = 16; o; o >>= 1) acc += __shfl_xor_sync(0xffffffffu, acc, o);
    if (lane == 0) g_b4[600 + w] = sb[w] - acc;
  }
}

// ---------------- pack weights k-major: g_W4T[i][o] = w_z[j][i], o=z*DD+j ----------------
__global__ void k_pack(const float* __restrict__ kw, const float* __restrict__ qw,
                       const float* __restrict__ vw, const float* __restrict__ sw) {
  int idx = blockIdx.x*blockDim.x + threadIdx.x;
  if (idx >= OUT4*DD) return;
  int i = idx / OUT4, o = idx - i*OUT4;
  int z = o / DD, j = o - z*DD;
  const float* w = (z==0)?kw:(z==1)?qw:(z==2)?vw:sw;
  g_W4T[idx] = w[(size_t)j*DD + i];
}

// ---------------- transpose X [NN][DD] -> g_XT [DD][NN] ----------------
__global__ void k_transX(const float* __restrict__ X) {
  __shared__ float t[32][33];
  int bx = blockIdx.x*32;   // n base
  int by = blockIdx.y*32;   // d base
  int tx = threadIdx.x, ty = threadIdx.y;
  #pragma unroll
  for (int i = 0; i < 32; i += 8) {
    int n = bx + ty + i, d = by + tx;
    t[ty+i][tx] = (n < NN && d < DD) ? X[(size_t)n*DD + d] : 0.f;
  }
  __syncthreads();
  #pragma unroll
  for (int i = 0; i < 32; i += 8) {
    int d = by + ty + i, n = bx + tx;
    if (d < DD && n < NN) g_XT[(size_t)d*NN + n] = t[tx][ty+i];
  }
}

// ---------------- transpose wR [200][200] -> g_WRT [i][j] ----------------
__global__ void k_transR(const float* __restrict__ W) {
  __shared__ float t[32][33];
  int bx = blockIdx.x*32;   // j base (rows of W)
  int by = blockIdx.y*32;   // i base (cols of W)
  int tx = threadIdx.x, ty = threadIdx.y;
  #pragma unroll
  for (int i = 0; i < 32; i += 8) {
    int j = bx + ty + i, c = by + tx;
    t[ty+i][tx] = (j < DD && c < DD) ? W[(size_t)j*DD + c] : 0.f;
  }
  __syncthreads();
  #pragma unroll
  for (int i = 0; i < 32; i += 8) {
    int c = by + ty + i, j = bx + tx;
    if (c < DD && j < DD) g_WRT[(size_t)c*DD + j] = t[tx][ty+i];
  }
}

// ---------------- fused GEMM -> K,Q,V,S (f32x2, register-prefetch pipeline) ------------
#define GBM 128
#define GBN 128
#define GBK 40
#define NPH 5
#define GSTG (GBK*GBM)            // 5120 floats per matrix per buffer
#define GEMM_SMEM (4*GSTG*4)      // 81920 B : A0|A1|B0|B1
__global__ __launch_bounds__(256) void k_gemm() {
  extern __shared__ __align__(16) float sm[];
  float* Ab[2] = { sm,            sm + GSTG   };
  float* Bb[2] = { sm + 2*GSTG,   sm + 3*GSTG };
  int row0 = blockIdx.x*GBM, col0 = blockIdx.y*GBN;
  int tid = threadIdx.x;
  int r5 = tid >> 5, c5 = tid & 31;       // per-l: row = r5 + l*8, col = c5
  int gm = row0 + c5*4;
  int go = col0 + c5*4;
  bool okA = (gm + 3 < NN);
  bool okB = (go + 3 < OUT4);

  float4 rA[5], rB[5];
  #define LD_PH(s) do { \
    int k0 = (s)*GBK; \
    _Pragma("unroll") \
    for (int l = 0; l < 5; l++) { \
      int r = r5 + l*8; \
      rA[l] = okA ? *(const float4*)(g_XT  + (size_t)(k0+r)*NN   + gm) \
                  : make_float4(0.f,0.f,0.f,0.f); \
      rB[l] = okB ? *(const float4*)(g_W4T + (size_t)(k0+r)*OUT4 + go) \
                  : make_float4(0.f,0.f,0.f,0.f); \
    } \
  } while(0)
  #define ST_PH(b) do { \
    _Pragma("unroll") \
    for (int l = 0; l < 5; l++) { \
      int r = r5 + l*8; \
      *(float4*)&Ab[b][r*GBM + c5*4] = rA[l]; \
      *(float4*)&Bb[b][r*GBN + c5*4] = rB[l]; \
    } \
  } while(0)

  // 4x2 warps, 4x8 lanes, 8x8 thread tile
  int w = tid >> 5, lane = tid & 31;
  int wm = w & 3, wn = w >> 2;
  int lm = lane >> 3, ln = lane & 7;
  int m0 = wm*32 + lm*8;
  int n0 = wn*64 + ln*8;

  ULL acc[8][4];
  #pragma unroll
  for (int u = 0; u < 8; u++)
    #pragma unroll
    for (int v = 0; v < 4; v++) acc[u][v] = pk2(0.f, 0.f);

  LD_PH(0); ST_PH(0);
  __syncthreads();
  #pragma unroll
  for (int s = 0; s < NPH; s++) {
    int b = s & 1;
    if (s + 1 < NPH) LD_PH(s+1);      // LDG in flight during compute below
    const float* A = Ab[b];
    const float* B = Bb[b];
    #pragma unroll 4
    for (int kk = 0; kk < GBK; kk++) {
      float4 a0 = *(const float4*)&A[kk*GBM + m0];
      float4 a1 = *(const float4*)&A[kk*GBM + m0 + 4];
      float4 b0 = *(const float4*)&B[kk*GBN + n0];
      float4 b1 = *(const float4*)&B[kk*GBN + n0 + 4];
      ULL bb[4];
      bb[0] = ((const ULL*)&b0)[0]; bb[1] = ((const ULL*)&b0)[1];
      bb[2] = ((const ULL*)&b1)[0]; bb[3] = ((const ULL*)&b1)[1];
      float av[8] = {a0.x,a0.y,a0.z,a0.w,a1.x,a1.y,a1.z,a1.w};
      #pragma unroll
      for (int u = 0; u < 8; u++) {
        ULL aa = pk2(av[u], av[u]);
        #pragma unroll
        for (int v = 0; v < 4; v++) fma2(acc[u][v], aa, bb[v]);
      }
    }
    if (s + 1 < NPH) ST_PH((s+1)&1);  // other buffer; prior readers done (sync below)
    __syncthreads();
  }

  // epilogue: 8 rows x 8 cols per thread; cols never straddle a z-boundary (200%8==0)
  int o0 = col0 + n0;
  if (o0 < OUT4) {
    int z = o0 / DD, j0 = o0 - z*DD;
    float4 bi0 = *(const float4*)&g_b4[o0];
    float4 bi1 = *(const float4*)&g_b4[o0+4];
    float* outb = g_KQVS + (size_t)z*NN*DD + j0;
    #pragma unroll
    for (int u = 0; u < 8; u++) {
      int n = row0 + m0 + u;
      if (n >= NN) continue;
      float c0,c1,c2,c3,c4,c5v,c6,c7;
      upk2(acc[u][0], c0, c1); upk2(acc[u][1], c2, c3);
      upk2(acc[u][2], c4, c5v); upk2(acc[u][3], c6, c7);
      float4 s0 = make_float4(c0+bi0.x, c1+bi0.y, c2+bi0.z, c3+bi0.w);
      float4 s1 = make_float4(c4+bi1.x, c5v+bi1.y, c6+bi1.z, c7+bi1.w);
      *(float4*)(outb + (size_t)n*DD)     = s0;
      *(float4*)(outb + (size_t)n*DD + 4) = s1;
    }
  }
  #undef LD_PH
  #undef ST_PH
}

// ---------------- init counters ----------------
__global__ void k_init() {
  int stride = gridDim.x*blockDim.x;
  int t0 = blockIdx.x*blockDim.x + threadIdx.x;
  for (int t = t0; t < NN; t += stride) {
    g_maxu[t] = 0x007FFFFFu;   // enc(-inf)
    g_cnt2[t] = 0; g_cur2[t] = 0;
  }
  for (int t = t0; t < RR; t += stride) { g_cnt[t] = 0; g_cur[t] = 0; }
  for (int t = t0; t < DD; t += stride) { g_colsum[t] = 0.f; g_colsum2[t] = 0.f; }
}

// ---------------- M_r = sum_b w_comp[r,b] * A_b  (register-cached) ----------------
__global__ __launch_bounds__(256) void k_compM(const float* __restrict__ A,
                                               const float* __restrict__ wc) {
  __shared__ float wsh[RR*BB];   // 20KB
  int tid = threadIdx.x;
  for (int idx = tid; idx < RR*BB; idx += 256) wsh[idx] = wc[idx];
  __syncthreads();
  int n = blockIdx.x*256 + tid;
  if (n >= DD*DD) return;
  float a[BB];
  #pragma unroll
  for (int b = 0; b < BB; b++) a[b] = A[(size_t)b*DD*DD + n];
  for (int r = 0; r < RR; r++) {
    float acc0 = 0.f, acc1 = 0.f;
    const float* wr = wsh + r*BB;
    #pragma unroll
    for (int b = 0; b < BB; b += 2) {
      acc0 = fmaf(wr[b],   a[b],   acc0);
      acc1 = fmaf(wr[b+1], a[b+1], acc1);
    }
    g_M[(size_t)r*DD*DD + n] = acc0 + acc1;
  }
}

// ---------------- histograms: by relation AND by dst ----------------
__global__ void k_hist(const int* __restrict__ et, const int* __restrict__ dst) {
  int e = blockIdx.x*blockDim.x + threadIdx.x;
  if (e < EE) {
    atomicAdd(&g_cnt[et[e]], 1);
    atomicAdd(&g_cnt2[dst[e]], 1);
  }
}
__global__ void k_scan() {
  if (threadIdx.x == 0) {
    int s = 0;
    for (int r = 0; r < RR; r++) { g_off[r] = s; s += g_cnt[r]; }
    g_off[RR] = s;
  }
}
// 1-block exclusive scan of g_cnt2[NN] -> g_off2
#define SC_CHUNK 30
__global__ __launch_bounds__(1024) void k_scan2() {
  __shared__ int ps[1024];
  int t = threadIdx.x;
  int base = t*SC_CHUNK;
  int s = 0;
  #pragma unroll
  for (int i = 0; i < SC_CHUNK; i++) { int idx = base+i; if (idx < NN) s += g_cnt2[idx]; }
  ps[t] = s;
  __syncthreads();
  for (int off = 1; off < 1024; off <<= 1) {
    int v = ps[t];
    int add = (t >= off) ? ps[t-off] : 0;
    __syncthreads();
    ps[t] = v + add;
    __syncthreads();
  }
  int run = (t > 0) ? ps[t-1] : 0;
  #pragma unroll
  for (int i = 0; i < SC_CHUNK; i++) {
    int idx = base+i;
    if (idx < NN) { g_off2[idx] = run; run += g_cnt2[idx]; }
  }
  if (t == 1023) g_off2[NN] = ps[1023];
}
__global__ void k_scatter(const int* __restrict__ et, const int* __restrict__ src,
                          const int* __restrict__ dst) {
  int e = blockIdx.x*blockDim.x + threadIdx.x;
  if (e < EE) {
    int t = et[e];
    int p = atomicAdd(&g_cur[t], 1);
    g_eid[g_off[t] + p] = e;
    int d = dst[e];
    int p2 = atomicAdd(&g_cur2[d], 1);
    int pos = g_off2[d] + p2;
    g_p2[e] = pos;
    g_src2[pos] = src[e];
  }
}

// ---------------- attention: att_e = k^T M_r q (f32x2), 256 thr, 4 rows/thread ----------
#define ABM 128
#define KST 204
#define ATT_SMEM ((ABM*KST + DD*64 + ABM*64 + ABM)*4 + 3*ABM*4)  // 190464 B
__global__ __launch_bounds__(256, 1) void k_att(const int* __restrict__ src,
                                                const int* __restrict__ dst) {
  extern __shared__ __align__(16) float sm[];
  float* k_sh   = sm;                 // [ABM][KST]
  float* Msh    = k_sh + ABM*KST;     // [DD][64] (reused as [DD][8] in remainder)
  float* q_t    = Msh + DD*64;        // [ABM][64] (reused as [ABM][8])
  float* att_sh = q_t + ABM*64;       // [ABM]
  int* es_src = (int*)(att_sh + ABM);
  int* es_dst = es_src + ABM;
  int* es_eid = es_dst + ABM;

  int r = blockIdx.x;
  int beg = g_off[r], end = g_off[r+1];
  int base = beg + blockIdx.y*ABM;
  if (base >= end) return;
  int m = end - base; if (m > ABM) m = ABM;
  int tid = threadIdx.x;
  if (tid < ABM) {
    int e = g_eid[base + ((tid < m) ? tid : 0)];
    es_eid[tid] = e;
    es_src[tid] = src[e];
    es_dst[tid] = dst[e];
    att_sh[tid] = 0.f;
  }
  __syncthreads();
  // gather K rows (float4) into padded smem
  for (int idx = tid; idx < ABM*(DD/4); idx += 256) {
    int e = idx / (DD/4), p = idx - e*(DD/4);
    *(float4*)(k_sh + e*KST + p*4) = *(const float4*)(g_KQVS + (size_t)es_src[e]*DD + p*4);
  }
  int tx = tid & 7;
  int ty = tid >> 3;        // 0..31, 4 rows each
  const float* Mr = g_M + (size_t)r*DD*DD;
  const float* Qbase = g_KQVS + (size_t)NN*DD;
  // --- 3 full 64-col tiles: cols 0..191 ---
  for (int jt = 0; jt < 3; jt++) {
    int j0 = jt*64;
    __syncthreads();
    for (int idx = tid; idx < DD*16; idx += 256) {
      int i = idx >> 4, p = idx & 15;
      *(float4*)(Msh + i*64 + p*4) = *(const float4*)(Mr + (size_t)i*DD + j0 + p*4);
    }
    for (int idx = tid; idx < ABM*16; idx += 256) {
      int e = idx >> 4, p = idx & 15;
      *(float4*)(q_t + e*64 + p*4) = *(const float4*)(Qbase + (size_t)es_dst[e]*DD + j0 + p*4);
    }
    __syncthreads();
    ULL acc[4][4];
    #pragma unroll
    for (int u = 0; u < 4; u++)
      #pragma unroll
      for (int v = 0; v < 4; v++) acc[u][v] = pk2(0.f, 0.f);
    #pragma unroll 4
    for (int kk = 0; kk < DD; kk++) {
      float4 b0 = *(const float4*)(Msh + kk*64 + tx*8);
      float4 b1 = *(const float4*)(Msh + kk*64 + tx*8 + 4);
      ULL bb0 = ((const ULL*)&b0)[0], bb1 = ((const ULL*)&b0)[1];
      ULL bb2 = ((const ULL*)&b1)[0], bb3 = ((const ULL*)&b1)[1];
      #pragma unroll
      for (int u = 0; u < 4; u++) {
        float a = k_sh[(ty*4+u)*KST + kk];
        ULL aa = pk2(a, a);
        fma2(acc[u][0], aa, bb0); fma2(acc[u][1], aa, bb1);
        fma2(acc[u][2], aa, bb2); fma2(acc[u][3], aa, bb3);
      }
    }
    #pragma unroll
    for (int u = 0; u < 4; u++) {
      float4 q0 = *(const float4*)(q_t + (ty*4+u)*64 + tx*8);
      float4 q1 = *(const float4*)(q_t + (ty*4+u)*64 + tx*8 + 4);
      float c0,c1,c2,c3,c4,c5,c6,c7;
      upk2(acc[u][0], c0, c1); upk2(acc[u][1], c2, c3);
      upk2(acc[u][2], c4, c5); upk2(acc[u][3], c6, c7);
      float p = c0*q0.x + c1*q0.y + c2*q0.z + c3*q0.w
              + c4*q1.x + c5*q1.y + c6*q1.z + c7*q1.w;
      p += __shfl_xor_sync(0xffffffffu, p, 1);
      p += __shfl_xor_sync(0xffffffffu, p, 2);
      p += __shfl_xor_sync(0xffffffffu, p, 4);
      if (tx == 0) att_sh[ty*4+u] += p;
    }
  }
  // --- remainder: cols 192..199 (8 cols), 2 threads per edge ---
  __syncthreads();
  for (int idx = tid; idx < DD*2; idx += 256) {
    int i = idx >> 1, p = idx & 1;
    *(float4*)(Msh + i*8 + p*4) = *(const float4*)(Mr + (size_t)i*DD + 192 + p*4);
  }
  for (int idx = tid; idx < ABM*2; idx += 256) {
    int e = idx >> 1, p = idx & 1;
    *(float4*)(q_t + e*8 + p*4) = *(const float4*)(Qbase + (size_t)es_dst[e]*DD + 192 + p*4);
  }
  __syncthreads();
  {
    int e = tid >> 1, half = tid & 1;
    ULL acc0 = pk2(0.f,0.f), acc1 = pk2(0.f,0.f);
    const float* krow = k_sh + e*KST;
    #pragma unroll 4
    for (int kk = 0; kk < DD; kk++) {
      float a = krow[kk];
      ULL aa = pk2(a, a);
      float4 mv = *(const float4*)(Msh + kk*8 + half*4);
      fma2(acc0, aa, ((const ULL*)&mv)[0]);
      fma2(acc1, aa, ((const ULL*)&mv)[1]);
    }
    float4 qv = *(const float4*)(q_t + e*8 + half*4);
    float s0,s1,s2,s3; upk2(acc0,s0,s1); upk2(acc1,s2,s3);
    float p = s0*qv.x + s1*qv.y + s2*qv.z + s3*qv.w;
    p += __shfl_xor_sync(0xffffffffu, p, 1);
    if (half == 0) att_sh[e] += p;
  }
  __syncthreads();
  if (tid < m) {
    float a = att_sh[tid];
    int e = es_eid[tid];
    g_att2[g_p2[e]] = a;    // write into dst-sorted order
    unsigned u = __float_as_uint(a);
    u = (u & 0x80000000u) ? ~u : (u | 0x80000000u);
    atomicMax(&g_maxu[es_dst[tid]], u);
  }
}

// ---------------- per-dst softmax + weighted V aggregation + S merge (no atomics) --------
__device__ __forceinline__ float decf(unsigned u) {
  return (u & 0x80000000u) ? __uint_as_float(u ^ 0x80000000u) : __uint_as_float(~u);
}
__global__ __launch_bounds__(128) void k_agg2() {
  int d = blockIdx.x;
  int beg = g_off2[d], end = g_off2[d+1];
  int t = threadIdx.x;   // t<100 active for 2 cols each
  float m = decf(g_maxu[d]);
  float denom = 0.f;
  float ax = 0.f, ay = 0.f;
  const float* Vbase = g_KQVS + (size_t)2*NN*DD;
  if (beg < end) {
    float a_cur = g_att2[beg];
    int   s_cur = g_src2[beg];
    for (int i = beg; i < end; i++) {
      float a_nxt = 0.f; int s_nxt = 0;
      if (i + 1 < end) { a_nxt = g_att2[i+1]; s_nxt = g_src2[i+1]; }  // prefetch
      float ex = __expf(a_cur - m);
      denom += ex;
      if (t < 100) {
        float2 v = *(const float2*)(Vbase + (size_t)s_cur*DD + t*2);
        ax = fmaf(ex, v.x, ax);
        ay = fmaf(ex, v.y, ay);
      }
      a_cur = a_nxt; s_cur = s_nxt;
    }
  }
  if (t < 100) {
    float inv = (1.f/3.f) / fmaxf(denom, 1e-30f);
    size_t off = (size_t)d*DD + t*2;
    const float* Sb = g_KQVS + (size_t)3*NN*DD;
    float2 sv = *(const float2*)(Sb + off);
    float2 o;
    o.x = sv.x*(1.f/3.f) + ax*inv;
    o.y = sv.y*(1.f/3.f) + ay*inv;
    *(float2*)(g_agg + off) = o;
  }
}

// ---------------- column stats ----------------
#define ST_ROWS 48
__global__ __launch_bounds__(256) void k_stats() {
  int c = threadIdx.x;
  int r0 = blockIdx.x*ST_ROWS;
  if (c >= DD) return;
  float s = 0.f, s2 = 0.f;
  int rmax = NN - r0; if (rmax > ST_ROWS) rmax = ST_ROWS;
  for (int lr = 0; lr < rmax; lr++) {
    float val = g_agg[(size_t)(r0+lr)*DD + c];
    s += val; s2 = fmaf(val, val, s2);
  }
  atomicAdd(&g_colsum[c], s);
  atomicAdd(&g_colsum2[c], s2);
}
__global__ void k_bnprep(const float* __restrict__ gamma, const float* __restrict__ beta) {
  int c = threadIdx.x;
  if (c < DD) {
    float mean = g_colsum[c] * (1.f/NN);
    float var  = g_colsum2[c] * (1.f/NN) - mean*mean;
    float sc = gamma[c] * rsqrtf(var + 1e-5f);
    g_scale[c] = sc;
    g_shift[c] = beta[c] - mean*sc;
  }
}
__global__ void k_bnout(float* __restrict__ out) {
  int idx = blockIdx.x*blockDim.x + threadIdx.x;
  if (idx < NN*DD) {
    int c = idx - (idx/DD)*DD;
    float y = g_agg[idx]*g_scale[c] + g_shift[c];
    float t;
    asm("tanh.approx.f32 %0, %1;" : "=f"(t) : "f"(y));
    out[idx] = t;
  }
}

// ---------------- r_out = r_feats @ wR^T + b (coalesced via transposed wR) --------------
__global__ void k_rout(const float* __restrict__ rf,
                       const float* __restrict__ br, float* __restrict__ out) {
  __shared__ float xs[DD];
  int r = blockIdx.x;
  int tid = threadIdx.x;
  if (tid < DD) xs[tid] = rf[(size_t)r*DD + tid];
  __syncthreads();
  if (tid < DD) {
    float acc = br[tid];
    for (int i = 0; i < DD; i++) acc = fmaf(xs[i], g_WRT[(size_t)i*DD + tid], acc);
    out[(size_t)r*DD + tid] = acc;
  }
}

// ---------------- launcher ----------------
extern "C" void kernel_launch(void* const* d_in, const int* in_sizes, int n_in,
                              void* d_out, int out_size) {
  const float* n_in_feats = (const float*)d_in[0];
  const float* r_feats    = (const float*)d_in[1];
  const float* loop_rel   = (const float*)d_in[3];
  const float* rel_att    = (const float*)d_in[4];
  const float* w_comp     = (const float*)d_in[5];
  const float* wS_w = (const float*)d_in[10]; const float* wS_b = (const float*)d_in[11];
  const float* wR_w = (const float*)d_in[12]; const float* wR_b = (const float*)d_in[13];
  const float* k_w  = (const float*)d_in[14]; const float* k_b  = (const float*)d_in[15];
  const float* q_w  = (const float*)d_in[16]; const float* q_b  = (const float*)d_in[17];
  const float* v_w  = (const float*)d_in[18]; const float* v_b  = (const float*)d_in[19];
  const float* gamma = (const float*)d_in[20]; const float* beta = (const float*)d_in[21];
  const int* src   = (const int*)d_in[22];
  const int* dst   = (const int*)d_in[23];
  const int* etype = (const int*)d_in[24];
  float* out = (float*)d_out;

  cudaFuncSetAttribute(k_gemm, cudaFuncAttributeMaxDynamicSharedMemorySize, GEMM_SMEM);
  cudaFuncSetAttribute(k_att,  cudaFuncAttributeMaxDynamicSharedMemorySize, ATT_SMEM);

  k_packb<<<25, 256>>>(k_b, q_b, v_b, wS_b, loop_rel, wS_w);
  k_pack<<<(OUT4*DD + 255)/256, 256>>>(k_w, q_w, v_w, wS_w);
  {
    dim3 g((NN + 31)/32, (DD + 31)/32);
    k_transX<<<g, dim3(32, 8)>>>(n_in_feats);
  }
  {
    dim3 g((NN + GBM - 1)/GBM, (OUT4 + GBN - 1)/GBN);
    k_gemm<<<g, 256, GEMM_SMEM>>>();      // 4th launch -> ncu capture slot
  }
  {
    dim3 g((DD + 31)/32, (DD + 31)/32);
    k_transR<<<g, dim3(32, 8)>>>(wR_w);
  }
  k_init<<<256, 256>>>();
  k_compM<<<(DD*DD + 255)/256, 256>>>(rel_att, w_comp);
  k_hist<<<(EE+255)/256, 256>>>(etype, dst);
  k_scan<<<1, 32>>>();
  k_scan2<<<1, 1024>>>();
  k_scatter<<<(EE+255)/256, 256>>>(etype, src, dst);
  {
    dim3 g(RR, 16);
    k_att<<<g, 256, ATT_SMEM>>>(src, dst);
  }
  k_agg2<<<NN, 128>>>();
  k_stats<<<(NN + ST_ROWS - 1)/ST_ROWS, 256>>>();
  k_bnprep<<<1, 256>>>(gamma, beta);
  k_bnout<<<(NN*DD + 255)/256, 256>>>(out);
  k_rout<<<RR, 256>>>(r_feats, wR_b, out + (size_t)NN*DD);
}

// round 15
// speedup vs baseline: 1.9742x; 1.0093x over previous
#include <cuda_runtime.h>
#include <cstdint>
#include <math.h>

#define NN 30000
#define EE 100000
#define DD 200
#define RR 100
#define BB 50
#define OUT4 (4*DD)   // 800 packed output columns: k,q,v,s

typedef unsigned long long ULL;

// ---------------- packed f32x2 helpers (FFMA2: 2x fp32 FMA throughput) ----------------
__device__ __forceinline__ ULL pk2(float a, float b) {
  ULL r; asm("mov.b64 %0,{%1,%2};" : "=l"(r) : "f"(a), "f"(b)); return r;
}
__device__ __forceinline__ void upk2(ULL d, float& x, float& y) {
  asm("mov.b64 {%0,%1},%2;" : "=f"(x), "=f"(y) : "l"(d));
}
__device__ __forceinline__ void fma2(ULL& d, ULL a, ULL b) {
  asm("fma.rn.f32x2 %0,%1,%2,%0;" : "+l"(d) : "l"(a), "l"(b));
}

// ---------------- scratch (static device globals; no runtime alloc) ----------------
__device__ __align__(16) float g_M[RR*DD*DD];        // per-relation matrices, 16MB
__device__ __align__(16) float g_W4T[DD*OUT4];       // packed weights, k-major [200][800]
__device__ __align__(16) float g_XT[DD*NN];          // transposed X, k-major [200][30000]
__device__ __align__(16) float g_WRT[DD*DD];         // transposed wR, k-major [200][200]
__device__ float g_b4[OUT4];
__device__ __align__(16) float g_KQVS[4u*NN*DD];     // K|Q|V|S node features, 96MB
__device__ unsigned g_maxu[NN];
__device__ __align__(16) float g_agg[NN*DD];         // n_pre (merged) output
__device__ int g_cnt[RR];
__device__ int g_off[RR+1];
__device__ int g_cur[RR];
__device__ int g_eid[EE];
__device__ int g_cnt2[NN];      // dst histogram
__device__ int g_off2[NN+1];
__device__ int g_cur2[NN];
__device__ int g_p2[EE];        // e -> dst-sorted position
__device__ int g_src2[EE];      // src, dst-sorted
__device__ float g_att2[EE];    // att, dst-sorted
__device__ float g_colsum[DD];
__device__ float g_colsum2[DD];
__device__ float g_scale[DD];
__device__ float g_shift[DD];

// ---------------- biases: k/q/v elementwise; S bias folds -(loop_rel @ wS^T) ----------------
__global__ void k_packb(const float* __restrict__ kb, const float* __restrict__ qb,
                        const float* __restrict__ vb, const float* __restrict__ sb,
                        const float* __restrict__ loop, const float* __restrict__ sw) {
  int tid = threadIdx.x, blk = blockIdx.x;
  int g = blk*256 + tid;
  if (g < 600) {
    int z = g / DD, j = g - z*DD;
    g_b4[g] = (z==0)?kb[j]:(z==1)?qb[j]:vb[j];
  }
  int w = blk*8 + (tid >> 5);
  int lane = tid & 31;
  if (w < DD) {
    float acc = 0.f;
    for (int i = lane; i < DD; i += 32) acc = fmaf(loop[i], sw[(size_t)w*DD + i], acc);
    #pragma unroll
    for (int o = 16; o; o >>= 1) acc += __shfl_xor_sync(0xffffffffu, acc, o);
    if (lane == 0) g_b4[600 + w] = sb[w] - acc;
  }
}

// ---------------- pack weights k-major: g_W4T[i][o] = w_z[j][i], o=z*DD+j ----------------
__global__ void k_pack(const float* __restrict__ kw, const float* __restrict__ qw,
                       const float* __restrict__ vw, const float* __restrict__ sw) {
  int idx = blockIdx.x*blockDim.x + threadIdx.x;
  if (idx >= OUT4*DD) return;
  int i = idx / OUT4, o = idx - i*OUT4;
  int z = o / DD, j = o - z*DD;
  const float* w = (z==0)?kw:(z==1)?qw:(z==2)?vw:sw;
  g_W4T[idx] = w[(size_t)j*DD + i];
}

// ---------------- transpose X [NN][DD] -> g_XT [DD][NN] ----------------
__global__ void k_transX(const float* __restrict__ X) {
  __shared__ float t[32][33];
  int bx = blockIdx.x*32;   // n base
  int by = blockIdx.y*32;   // d base
  int tx = threadIdx.x, ty = threadIdx.y;
  #pragma unroll
  for (int i = 0; i < 32; i += 8) {
    int n = bx + ty + i, d = by + tx;
    t[ty+i][tx] = (n < NN && d < DD) ? X[(size_t)n*DD + d] : 0.f;
  }
  __syncthreads();
  #pragma unroll
  for (int i = 0; i < 32; i += 8) {
    int d = by + ty + i, n = bx + tx;
    if (d < DD && n < NN) g_XT[(size_t)d*NN + n] = t[tx][ty+i];
  }
}

// ---------------- transpose wR [200][200] -> g_WRT [i][j] ----------------
__global__ void k_transR(const float* __restrict__ W) {
  __shared__ float t[32][33];
  int bx = blockIdx.x*32;   // j base (rows of W)
  int by = blockIdx.y*32;   // i base (cols of W)
  int tx = threadIdx.x, ty = threadIdx.y;
  #pragma unroll
  for (int i = 0; i < 32; i += 8) {
    int j = bx + ty + i, c = by + tx;
    t[ty+i][tx] = (j < DD && c < DD) ? W[(size_t)j*DD + c] : 0.f;
  }
  __syncthreads();
  #pragma unroll
  for (int i = 0; i < 32; i += 8) {
    int c = by + ty + i, j = bx + tx;
    if (c < DD && j < DD) g_WRT[(size_t)c*DD + j] = t[tx][ty+i];
  }
}

// ---------------- fused GEMM -> K,Q,V,S (f32x2, 512 threads, 16 warps/SM) --------------
#define GBM 128
#define GBN 128
#define GBK 40
#define NPH 5
#define GSTG (GBK*GBM)            // 5120 floats per matrix per buffer
#define GEMM_SMEM (4*GSTG*4)      // 81920 B : A0|A1|B0|B1
__global__ __launch_bounds__(512) void k_gemm() {
  extern __shared__ __align__(16) float sm[];
  float* Ab[2] = { sm,            sm + GSTG   };
  float* Bb[2] = { sm + 2*GSTG,   sm + 3*GSTG };
  int row0 = blockIdx.x*GBM, col0 = blockIdx.y*GBN;
  int tid = threadIdx.x;
  // load mapping: per matrix 1280 float4s; idx = tid + l*512 (l<3, guard idx<1280)
  int gm_c = (tid & 31)*4;                  // col within tile row
  bool okA = (row0 + gm_c + 3 < NN);
  bool okB = (col0 + gm_c + 3 < OUT4);

  float4 rA[3], rB[3];
  #define LD_PH(s) do { \
    int k0 = (s)*GBK; \
    _Pragma("unroll") \
    for (int l = 0; l < 3; l++) { \
      int idx = tid + l*512; \
      if (idx < GSTG/4) { \
        int r = idx >> 5, c = idx & 31; \
        rA[l] = okA ? *(const float4*)(g_XT  + (size_t)(k0+r)*NN   + row0 + c*4) \
                    : make_float4(0.f,0.f,0.f,0.f); \
        rB[l] = okB ? *(const float4*)(g_W4T + (size_t)(k0+r)*OUT4 + col0 + c*4) \
                    : make_float4(0.f,0.f,0.f,0.f); \
      } \
    } \
  } while(0)
  #define ST_PH(b) do { \
    _Pragma("unroll") \
    for (int l = 0; l < 3; l++) { \
      int idx = tid + l*512; \
      if (idx < GSTG/4) { \
        int r = idx >> 5, c = idx & 31; \
        *(float4*)&Ab[b][r*GBM + c*4] = rA[l]; \
        *(float4*)&Bb[b][r*GBN + c*4] = rB[l]; \
      } \
    } \
  } while(0)

  // 4x4 warps (32x32 warp tile), lanes 4x8, 8x4 thread tile
  int w = tid >> 5, lane = tid & 31;
  int wm = w & 3, wn = w >> 2;
  int lm = lane >> 3, ln = lane & 7;
  int m0 = wm*32 + lm*8;
  int n0 = wn*32 + ln*4;

  ULL acc[8][2];
  #pragma unroll
  for (int u = 0; u < 8; u++) { acc[u][0] = pk2(0.f,0.f); acc[u][1] = pk2(0.f,0.f); }

  LD_PH(0); ST_PH(0);
  __syncthreads();
  #pragma unroll
  for (int s = 0; s < NPH; s++) {
    int b = s & 1;
    if (s + 1 < NPH) LD_PH(s+1);      // LDG in flight during compute below
    const float* A = Ab[b];
    const float* B = Bb[b];
    #pragma unroll 4
    for (int kk = 0; kk < GBK; kk++) {
      float4 a0 = *(const float4*)&A[kk*GBM + m0];
      float4 a1 = *(const float4*)&A[kk*GBM + m0 + 4];
      float4 b0 = *(const float4*)&B[kk*GBN + n0];
      ULL bb0 = ((const ULL*)&b0)[0], bb1 = ((const ULL*)&b0)[1];
      float av[8] = {a0.x,a0.y,a0.z,a0.w,a1.x,a1.y,a1.z,a1.w};
      #pragma unroll
      for (int u = 0; u < 8; u++) {
        ULL aa = pk2(av[u], av[u]);
        fma2(acc[u][0], aa, bb0);
        fma2(acc[u][1], aa, bb1);
      }
    }
    if (s + 1 < NPH) ST_PH((s+1)&1);  // other buffer; prior readers done (sync below)
    __syncthreads();
  }

  // epilogue: 8 rows x 4 cols per thread; 4-col groups never straddle z-boundary (200%4==0)
  int o0 = col0 + n0;
  if (o0 < OUT4) {
    int z = o0 / DD, j0 = o0 - z*DD;
    float4 bi = *(const float4*)&g_b4[o0];
    float* outb = g_KQVS + (size_t)z*NN*DD + j0;
    #pragma unroll
    for (int u = 0; u < 8; u++) {
      int n = row0 + m0 + u;
      if (n >= NN) continue;
      float c0,c1,c2,c3;
      upk2(acc[u][0], c0, c1); upk2(acc[u][1], c2, c3);
      *(float4*)(outb + (size_t)n*DD) =
        make_float4(c0+bi.x, c1+bi.y, c2+bi.z, c3+bi.w);
    }
  }
  #undef LD_PH
  #undef ST_PH
}

// ---------------- init counters ----------------
__global__ void k_init() {
  int stride = gridDim.x*blockDim.x;
  int t0 = blockIdx.x*blockDim.x + threadIdx.x;
  for (int t = t0; t < NN; t += stride) {
    g_maxu[t] = 0x007FFFFFu;   // enc(-inf)
    g_cnt2[t] = 0; g_cur2[t] = 0;
  }
  for (int t = t0; t < RR; t += stride) { g_cnt[t] = 0; g_cur[t] = 0; }
  for (int t = t0; t < DD; t += stride) { g_colsum[t] = 0.f; g_colsum2[t] = 0.f; }
}

// ---------------- M_r = sum_b w_comp[r,b] * A_b  (register-cached) ----------------
__global__ __launch_bounds__(256) void k_compM(const float* __restrict__ A,
                                               const float* __restrict__ wc) {
  __shared__ float wsh[RR*BB];   // 20KB
  int tid = threadIdx.x;
  for (int idx = tid; idx < RR*BB; idx += 256) wsh[idx] = wc[idx];
  __syncthreads();
  int n = blockIdx.x*256 + tid;
  if (n >= DD*DD) return;
  float a[BB];
  #pragma unroll
  for (int b = 0; b < BB; b++) a[b] = A[(size_t)b*DD*DD + n];
  for (int r = 0; r < RR; r++) {
    float acc0 = 0.f, acc1 = 0.f;
    const float* wr = wsh + r*BB;
    #pragma unroll
    for (int b = 0; b < BB; b += 2) {
      acc0 = fmaf(wr[b],   a[b],   acc0);
      acc1 = fmaf(wr[b+1], a[b+1], acc1);
    }
    g_M[(size_t)r*DD*DD + n] = acc0 + acc1;
  }
}

// ---------------- histograms: by relation AND by dst ----------------
__global__ void k_hist(const int* __restrict__ et, const int* __restrict__ dst) {
  int e = blockIdx.x*blockDim.x + threadIdx.x;
  if (e < EE) {
    atomicAdd(&g_cnt[et[e]], 1);
    atomicAdd(&g_cnt2[dst[e]], 1);
  }
}
__global__ void k_scan() {
  if (threadIdx.x == 0) {
    int s = 0;
    for (int r = 0; r < RR; r++) { g_off[r] = s; s += g_cnt[r]; }
    g_off[RR] = s;
  }
}
// 1-block exclusive scan of g_cnt2[NN] -> g_off2
#define SC_CHUNK 30
__global__ __launch_bounds__(1024) void k_scan2() {
  __shared__ int ps[1024];
  int t = threadIdx.x;
  int base = t*SC_CHUNK;
  int s = 0;
  #pragma unroll
  for (int i = 0; i < SC_CHUNK; i++) { int idx = base+i; if (idx < NN) s += g_cnt2[idx]; }
  ps[t] = s;
  __syncthreads();
  for (int off = 1; off < 1024; off <<= 1) {
    int v = ps[t];
    int add = (t >= off) ? ps[t-off] : 0;
    __syncthreads();
    ps[t] = v + add;
    __syncthreads();
  }
  int run = (t > 0) ? ps[t-1] : 0;
  #pragma unroll
  for (int i = 0; i < SC_CHUNK; i++) {
    int idx = base+i;
    if (idx < NN) { g_off2[idx] = run; run += g_cnt2[idx]; }
  }
  if (t == 1023) g_off2[NN] = ps[1023];
}
__global__ void k_scatter(const int* __restrict__ et, const int* __restrict__ src,
                          const int* __restrict__ dst) {
  int e = blockIdx.x*blockDim.x + threadIdx.x;
  if (e < EE) {
    int t = et[e];
    int p = atomicAdd(&g_cur[t], 1);
    g_eid[g_off[t] + p] = e;
    int d = dst[e];
    int p2 = atomicAdd(&g_cur2[d], 1);
    int pos = g_off2[d] + p2;
    g_p2[e] = pos;
    g_src2[pos] = src[e];
  }
}

// ---------------- attention: att_e = k^T M_r q (f32x2), 256 thr, 4 rows/thread ----------
#define ABM 128
#define KST 204
#define ATT_SMEM ((ABM*KST + DD*64 + ABM*64 + ABM)*4 + 3*ABM*4)  // 190464 B
__global__ __launch_bounds__(256, 1) void k_att(const int* __restrict__ src,
                                                const int* __restrict__ dst) {
  extern __shared__ __align__(16) float sm[];
  float* k_sh   = sm;                 // [ABM][KST]
  float* Msh    = k_sh + ABM*KST;     // [DD][64] (reused as [DD][8] in remainder)
  float* q_t    = Msh + DD*64;        // [ABM][64] (reused as [ABM][8])
  float* att_sh = q_t + ABM*64;       // [ABM]
  int* es_src = (int*)(att_sh + ABM);
  int* es_dst = es_src + ABM;
  int* es_eid = es_dst + ABM;

  int r = blockIdx.x;
  int beg = g_off[r], end = g_off[r+1];
  int base = beg + blockIdx.y*ABM;
  if (base >= end) return;
  int m = end - base; if (m > ABM) m = ABM;
  int tid = threadIdx.x;
  if (tid < ABM) {
    int e = g_eid[base + ((tid < m) ? tid : 0)];
    es_eid[tid] = e;
    es_src[tid] = src[e];
    es_dst[tid] = dst[e];
    att_sh[tid] = 0.f;
  }
  __syncthreads();
  // gather K rows (float4) into padded smem
  for (int idx = tid; idx < ABM*(DD/4); idx += 256) {
    int e = idx / (DD/4), p = idx - e*(DD/4);
    *(float4*)(k_sh + e*KST + p*4) = *(const float4*)(g_KQVS + (size_t)es_src[e]*DD + p*4);
  }
  int tx = tid & 7;
  int ty = tid >> 3;        // 0..31, 4 rows each
  const float* Mr = g_M + (size_t)r*DD*DD;
  const float* Qbase = g_KQVS + (size_t)NN*DD;
  // --- 3 full 64-col tiles: cols 0..191 ---
  for (int jt = 0; jt < 3; jt++) {
    int j0 = jt*64;
    __syncthreads();
    for (int idx = tid; idx < DD*16; idx += 256) {
      int i = idx >> 4, p = idx & 15;
      *(float4*)(Msh + i*64 + p*4) = *(const float4*)(Mr + (size_t)i*DD + j0 + p*4);
    }
    for (int idx = tid; idx < ABM*16; idx += 256) {
      int e = idx >> 4, p = idx & 15;
      *(float4*)(q_t + e*64 + p*4) = *(const float4*)(Qbase + (size_t)es_dst[e]*DD + j0 + p*4);
    }
    __syncthreads();
    ULL acc[4][4];
    #pragma unroll
    for (int u = 0; u < 4; u++)
      #pragma unroll
      for (int v = 0; v < 4; v++) acc[u][v] = pk2(0.f, 0.f);
    #pragma unroll 4
    for (int kk = 0; kk < DD; kk++) {
      float4 b0 = *(const float4*)(Msh + kk*64 + tx*8);
      float4 b1 = *(const float4*)(Msh + kk*64 + tx*8 + 4);
      ULL bb0 = ((const ULL*)&b0)[0], bb1 = ((const ULL*)&b0)[1];
      ULL bb2 = ((const ULL*)&b1)[0], bb3 = ((const ULL*)&b1)[1];
      #pragma unroll
      for (int u = 0; u < 4; u++) {
        float a = k_sh[(ty*4+u)*KST + kk];
        ULL aa = pk2(a, a);
        fma2(acc[u][0], aa, bb0); fma2(acc[u][1], aa, bb1);
        fma2(acc[u][2], aa, bb2); fma2(acc[u][3], aa, bb3);
      }
    }
    #pragma unroll
    for (int u = 0; u < 4; u++) {
      float4 q0 = *(const float4*)(q_t + (ty*4+u)*64 + tx*8);
      float4 q1 = *(const float4*)(q_t + (ty*4+u)*64 + tx*8 + 4);
      float c0,c1,c2,c3,c4,c5,c6,c7;
      upk2(acc[u][0], c0, c1); upk2(acc[u][1], c2, c3);
      upk2(acc[u][2], c4, c5); upk2(acc[u][3], c6, c7);
      float p = c0*q0.x + c1*q0.y + c2*q0.z + c3*q0.w
              + c4*q1.x + c5*q1.y + c6*q1.z + c7*q1.w;
      p += __shfl_xor_sync(0xffffffffu, p, 1);
      p += __shfl_xor_sync(0xffffffffu, p, 2);
      p += __shfl_xor_sync(0xffffffffu, p, 4);
      if (tx == 0) att_sh[ty*4+u] += p;
    }
  }
  // --- remainder: cols 192..199 (8 cols), 2 threads per edge ---
  __syncthreads();
  for (int idx = tid; idx < DD*2; idx += 256) {
    int i = idx >> 1, p = idx & 1;
    *(float4*)(Msh + i*8 + p*4) = *(const float4*)(Mr + (size_t)i*DD + 192 + p*4);
  }
  for (int idx = tid; idx < ABM*2; idx += 256) {
    int e = idx >> 1, p = idx & 1;
    *(float4*)(q_t + e*8 + p*4) = *(const float4*)(Qbase + (size_t)es_dst[e]*DD + 192 + p*4);
  }
  __syncthreads();
  {
    int e = tid >> 1, half = tid & 1;
    ULL acc0 = pk2(0.f,0.f), acc1 = pk2(0.f,0.f);
    const float* krow = k_sh + e*KST;
    #pragma unroll 4
    for (int kk = 0; kk < DD; kk++) {
      float a = krow[kk];
      ULL aa = pk2(a, a);
      float4 mv = *(const float4*)(Msh + kk*8 + half*4);
      fma2(acc0, aa, ((const ULL*)&mv)[0]);
      fma2(acc1, aa, ((const ULL*)&mv)[1]);
    }
    float4 qv = *(const float4*)(q_t + e*8 + half*4);
    float s0,s1,s2,s3; upk2(acc0,s0,s1); upk2(acc1,s2,s3);
    float p = s0*qv.x + s1*qv.y + s2*qv.z + s3*qv.w;
    p += __shfl_xor_sync(0xffffffffu, p, 1);
    if (half == 0) att_sh[e] += p;
  }
  __syncthreads();
  if (tid < m) {
    float a = att_sh[tid];
    int e = es_eid[tid];
    g_att2[g_p2[e]] = a;    // write into dst-sorted order
    unsigned u = __float_as_uint(a);
    u = (u & 0x80000000u) ? ~u : (u | 0x80000000u);
    atomicMax(&g_maxu[es_dst[tid]], u);
  }
}

// ---------------- per-dst softmax + weighted V aggregation + S merge (no atomics) --------
__device__ __forceinline__ float decf(unsigned u) {
  return (u & 0x80000000u) ? __uint_as_float(u ^ 0x80000000u) : __uint_as_float(~u);
}
__global__ __launch_bounds__(128) void k_agg2() {
  int d = blockIdx.x;
  int beg = g_off2[d], end = g_off2[d+1];
  int t = threadIdx.x;   // t<100 active for 2 cols each
  float m = decf(g_maxu[d]);
  float denom = 0.f;
  float ax = 0.f, ay = 0.f;
  const float* Vbase = g_KQVS + (size_t)2*NN*DD;
  if (beg < end) {
    float a_cur = g_att2[beg];
    int   s_cur = g_src2[beg];
    for (int i = beg; i < end; i++) {
      float a_nxt = 0.f; int s_nxt = 0;
      if (i + 1 < end) { a_nxt = g_att2[i+1]; s_nxt = g_src2[i+1]; }  // prefetch
      float ex = __expf(a_cur - m);
      denom += ex;
      if (t < 100) {
        float2 v = *(const float2*)(Vbase + (size_t)s_cur*DD + t*2);
        ax = fmaf(ex, v.x, ax);
        ay = fmaf(ex, v.y, ay);
      }
      a_cur = a_nxt; s_cur = s_nxt;
    }
  }
  if (t < 100) {
    float inv = (1.f/3.f) / fmaxf(denom, 1e-30f);
    size_t off = (size_t)d*DD + t*2;
    const float* Sb = g_KQVS + (size_t)3*NN*DD;
    float2 sv = *(const float2*)(Sb + off);
    float2 o;
    o.x = sv.x*(1.f/3.f) + ax*inv;
    o.y = sv.y*(1.f/3.f) + ay*inv;
    *(float2*)(g_agg + off) = o;
  }
}

// ---------------- column stats ----------------
#define ST_ROWS 48
__global__ __launch_bounds__(256) void k_stats() {
  int c = threadIdx.x;
  int r0 = blockIdx.x*ST_ROWS;
  if (c >= DD) return;
  float s = 0.f, s2 = 0.f;
  int rmax = NN - r0; if (rmax > ST_ROWS) rmax = ST_ROWS;
  for (int lr = 0; lr < rmax; lr++) {
    float val = g_agg[(size_t)(r0+lr)*DD + c];
    s += val; s2 = fmaf(val, val, s2);
  }
  atomicAdd(&g_colsum[c], s);
  atomicAdd(&g_colsum2[c], s2);
}
__global__ void k_bnprep(const float* __restrict__ gamma, const float* __restrict__ beta) {
  int c = threadIdx.x;
  if (c < DD) {
    float mean = g_colsum[c] * (1.f/NN);
    float var  = g_colsum2[c] * (1.f/NN) - mean*mean;
    float sc = gamma[c] * rsqrtf(var + 1e-5f);
    g_scale[c] = sc;
    g_shift[c] = beta[c] - mean*sc;
  }
}
__global__ void k_bnout(float* __restrict__ out) {
  int idx = blockIdx.x*blockDim.x + threadIdx.x;
  if (idx < NN*DD) {
    int c = idx - (idx/DD)*DD;
    float y = g_agg[idx]*g_scale[c] + g_shift[c];
    float t;
    asm("tanh.approx.f32 %0, %1;" : "=f"(t) : "f"(y));
    out[idx] = t;
  }
}

// ---------------- r_out = r_feats @ wR^T + b (coalesced via transposed wR) --------------
__global__ void k_rout(const float* __restrict__ rf,
                       const float* __restrict__ br, float* __restrict__ out) {
  __shared__ float xs[DD];
  int r = blockIdx.x;
  int tid = threadIdx.x;
  if (tid < DD) xs[tid] = rf[(size_t)r*DD + tid];
  __syncthreads();
  if (tid < DD) {
    float acc = br[tid];
    for (int i = 0; i < DD; i++) acc = fmaf(xs[i], g_WRT[(size_t)i*DD + tid], acc);
    out[(size_t)r*DD + tid] = acc;
  }
}

// ---------------- launcher ----------------
extern "C" void kernel_launch(void* const* d_in, const int* in_sizes, int n_in,
                              void* d_out, int out_size) {
  const float* n_in_feats = (const float*)d_in[0];
  const float* r_feats    = (const float*)d_in[1];
  const float* loop_rel   = (const float*)d_in[3];
  const float* rel_att    = (const float*)d_in[4];
  const float* w_comp     = (const float*)d_in[5];
  const float* wS_w = (const float*)d_in[10]; const float* wS_b = (const float*)d_in[11];
  const float* wR_w = (const float*)d_in[12]; const float* wR_b = (const float*)d_in[13];
  const float* k_w  = (const float*)d_in[14]; const float* k_b  = (const float*)d_in[15];
  const float* q_w  = (const float*)d_in[16]; const float* q_b  = (const float*)d_in[17];
  const float* v_w  = (const float*)d_in[18]; const float* v_b  = (const float*)d_in[19];
  const float* gamma = (const float*)d_in[20]; const float* beta = (const float*)d_in[21];
  const int* src   = (const int*)d_in[22];
  const int* dst   = (const int*)d_in[23];
  const int* etype = (const int*)d_in[24];
  float* out = (float*)d_out;

  cudaFuncSetAttribute(k_gemm, cudaFuncAttributeMaxDynamicSharedMemorySize, GEMM_SMEM);
  cudaFuncSetAttribute(k_att,  cudaFuncAttributeMaxDynamicSharedMemorySize, ATT_SMEM);

  k_packb<<<25, 256>>>(k_b, q_b, v_b, wS_b, loop_rel, wS_w);
  k_pack<<<(OUT4*DD + 255)/256, 256>>>(k_w, q_w, v_w, wS_w);
  {
    dim3 g((NN + 31)/32, (DD + 31)/32);
    k_transX<<<g, dim3(32, 8)>>>(n_in_feats);
  }
  {
    dim3 g((NN + GBM - 1)/GBM, (OUT4 + GBN - 1)/GBN);
    k_gemm<<<g, 512, GEMM_SMEM>>>();      // 4th launch -> ncu capture slot
  }
  {
    dim3 g((DD + 31)/32, (DD + 31)/32);
    k_transR<<<g, dim3(32, 8)>>>(wR_w);
  }
  k_init<<<256, 256>>>();
  k_compM<<<(DD*DD + 255)/256, 256>>>(rel_att, w_comp);
  k_hist<<<(EE+255)/256, 256>>>(etype, dst);
  k_scan<<<1, 32>>>();
  k_scan2<<<1, 1024>>>();
  k_scatter<<<(EE+255)/256, 256>>>(etype, src, dst);
  {
    dim3 g(RR, 16);
    k_att<<<g, 256, ATT_SMEM>>>(src, dst);
  }
  k_agg2<<<NN, 128>>>();
  k_stats<<<(NN + ST_ROWS - 1)/ST_ROWS, 256>>>();
  k_bnprep<<<1, 256>>>(gamma, beta);
  k_bnout<<<(NN*DD + 255)/256, 256>>>(out);
  k_rout<<<RR, 256>>>(r_feats, wR_b, out + (size_t)NN*DD);
}